// round 12
// baseline (speedup 1.0000x reference)
#include <cuda_runtime.h>
#include <cstdint>

// Problem constants
#define ROWS  65536      // B*N rows
#define NPTS  16384      // N
#define EPB   131072     // E per batch (N*K)
#define KNN   8
#define GRIDX 512        // ROWS / 128 row-blocks per GEMM

// ---------------- scratch (device globals; no allocation allowed) ----------
__device__ float g_x0[ROWS * 32];
__device__ float g_x1[ROWS * 64];
__device__ float g_x2[ROWS * 128];
__device__ float g_x3[ROWS * 256];
__device__ float g_za[ROWS * 256];
__device__ float g_zb[ROWS * 256];
__device__ float g_zc[ROWS];
__device__ float g_pa[256 * GRIDX * 2];   // stat partials (branch a): [ch*GRIDX+blk], sumsq at +COUT*GRIDX
__device__ float g_pb[256 * GRIDX * 2];   // stat partials (branch b)
__device__ float g_sa[256], g_ha[256];    // BN scale/shift branch a
__device__ float g_sb[256], g_hb[256];    // BN scale/shift branch b

// ---------------- f32x2 helpers --------------------------------------------
__device__ __forceinline__ unsigned long long pack_dup(float a) {
    unsigned long long r;
    unsigned int ab = __float_as_uint(a);
    asm("mov.b64 %0, {%1, %1};" : "=l"(r) : "r"(ab));
    return r;
}
__device__ __forceinline__ float f2lo(unsigned long long v) {
    return __uint_as_float((unsigned int)(v & 0xffffffffULL));
}
__device__ __forceinline__ float f2hi(unsigned long long v) {
    return __uint_as_float((unsigned int)(v >> 32));
}

// ---------------- GEMM: C[ROWS,COUT] = A[ROWS,CIN] @ W[CIN,COUT] ------------
// Thread (tx,ty): rows ty*8..+7, column pairs {tx*2 + 32*j} -> conflict-free
// LDS.64 on Ws (16 lanes x stride 2 floats covers all 32 banks once).
// STATS: fused per-block column sum/sumsq partials -> part.
template <int CIN, int COUT, bool STATS>
__global__ void __launch_bounds__(256) gemm_k(const float* __restrict__ A,
                                              const float* __restrict__ W,
                                              float* __restrict__ C,
                                              float* __restrict__ part) {
    constexpr int BM = 128;
    constexpr int BN = (COUT < 128) ? COUT : 128;
    constexpr int TM = 8;
    constexpr int TN = BN / 16;           // 2, 4, or 8
    constexpr int NJ = TN / 2;            // column pairs per thread
    constexpr int BK = 8;

    __shared__ float sh[BM * BK + BK * BN];   // As | Ws ; reused for stat reduce
    float* As = sh;                            // [BM][BK]
    float* Ws = sh + BM * BK;                  // [BK][BN]

    const int t   = threadIdx.x;
    const int tx  = t & 15;
    const int ty  = t >> 4;
    const int row0 = blockIdx.x * BM;
    const int col0 = blockIdx.y * BN;

    unsigned long long acc[TM][NJ];
#pragma unroll
    for (int m = 0; m < TM; m++)
#pragma unroll
        for (int j = 0; j < NJ; j++) acc[m][j] = 0ULL;

    for (int k0 = 0; k0 < CIN; k0 += BK) {
#pragma unroll
        for (int idx = t; idx < BM * BK; idx += 256) {
            int r = idx >> 3, c = idx & 7;
            As[r * BK + c] = A[(row0 + r) * CIN + k0 + c];
        }
#pragma unroll
        for (int idx = t; idx < BK * BN; idx += 256) {
            int kr = idx / BN, c = idx % BN;
            Ws[kr * BN + c] = W[(k0 + kr) * COUT + col0 + c];
        }
        __syncthreads();

#pragma unroll
        for (int k = 0; k < BK; k++) {
            unsigned long long a2[TM];
#pragma unroll
            for (int m = 0; m < TM; m++)
                a2[m] = pack_dup(As[(ty * TM + m) * BK + k]);
            unsigned long long w2[NJ];
#pragma unroll
            for (int j = 0; j < NJ; j++)
                w2[j] = *reinterpret_cast<const unsigned long long*>(
                    &Ws[k * BN + tx * 2 + 32 * j]);
#pragma unroll
            for (int m = 0; m < TM; m++)
#pragma unroll
                for (int j = 0; j < NJ; j++)
                    asm("fma.rn.f32x2 %0, %1, %2, %0;"
                        : "+l"(acc[m][j]) : "l"(a2[m]), "l"(w2[j]));
        }
        __syncthreads();
    }

    // Store C
#pragma unroll
    for (int m = 0; m < TM; m++) {
        int r = row0 + ty * TM + m;
#pragma unroll
        for (int j = 0; j < NJ; j++)
            *reinterpret_cast<unsigned long long*>(
                &C[r * COUT + col0 + tx * 2 + 32 * j]) = acc[m][j];
    }

    if (STATS) {
        float* red = sh;   // 16 * BN floats (fits: BM*BK = 1024 >= 16*BN/2... total sh >= 16*BN)
        // ---- pass 1: column sums ----
#pragma unroll
        for (int j = 0; j < NJ; j++) {
            float s0 = 0.f, s1 = 0.f;
#pragma unroll
            for (int m = 0; m < TM; m++) { s0 += f2lo(acc[m][j]); s1 += f2hi(acc[m][j]); }
            red[ty * BN + tx * 2 + 32 * j]     = s0;
            red[ty * BN + tx * 2 + 32 * j + 1] = s1;
        }
        __syncthreads();
        if (t < BN) {
            float s = 0.f;
#pragma unroll
            for (int g = 0; g < 16; g++) s += red[g * BN + t];
            part[(col0 + t) * GRIDX + blockIdx.x] = s;
        }
        __syncthreads();
        // ---- pass 2: column sums of squares ----
#pragma unroll
        for (int j = 0; j < NJ; j++) {
            float s0 = 0.f, s1 = 0.f;
#pragma unroll
            for (int m = 0; m < TM; m++) {
                float lo = f2lo(acc[m][j]), hi = f2hi(acc[m][j]);
                s0 += lo * lo; s1 += hi * hi;
            }
            red[ty * BN + tx * 2 + 32 * j]     = s0;
            red[ty * BN + tx * 2 + 32 * j + 1] = s1;
        }
        __syncthreads();
        if (t < BN) {
            float s = 0.f;
#pragma unroll
            for (int g = 0; g < 16; g++) s += red[g * BN + t];
            part[COUT * GRIDX + (col0 + t) * GRIDX + blockIdx.x] = s;
        }
    }
}

// ---------------- BN stats stage 2 (parallel): one block per channel --------
__global__ void __launch_bounds__(256) stats2p_k(const float* __restrict__ part,
                                                 const float* __restrict__ gam,
                                                 const float* __restrict__ bet,
                                                 int cout, int nblk, float invM,
                                                 float* __restrict__ scale,
                                                 float* __restrict__ shift) {
    const int ch = blockIdx.x, t = threadIdx.x;
    const float* ps = part + (size_t)ch * nblk;
    const float* pq = part + (size_t)cout * nblk + (size_t)ch * nblk;
    float s = 0.f, s2 = 0.f;
    for (int i = t; i < nblk; i += 256) { s += ps[i]; s2 += pq[i]; }
#pragma unroll
    for (int o = 16; o; o >>= 1) {
        s  += __shfl_xor_sync(0xffffffffu, s, o);
        s2 += __shfl_xor_sync(0xffffffffu, s2, o);
    }
    __shared__ float sw[16];
    int w = t >> 5, l = t & 31;
    if (l == 0) { sw[w] = s; sw[8 + w] = s2; }
    __syncthreads();
    if (t == 0) {
        float a = 0.f, b = 0.f;
#pragma unroll
        for (int g = 0; g < 8; g++) { a += sw[g]; b += sw[8 + g]; }
        float m = a * invM;
        float v = fmaxf(b * invM - m * m, 0.f);
        float sc = gam[ch] * rsqrtf(v + 1e-5f);
        scale[ch] = sc;
        shift[ch] = bet[ch] - m * sc;
    }
}

// ---------------- edge-level stats for layer-0 branch b ---------------------
// d_e = zb[nbr_e] - zb[ctr_e] over 524288 edges, 32 channels.
// partial layout: part[ch*256 + blk], sumsq at part[32*256 + ch*256 + blk]
__global__ void __launch_bounds__(256) estats1_k(const float* __restrict__ zb,
                                                 const int* __restrict__ ei,
                                                 float* __restrict__ part) {
    __shared__ float sh[512];
    const int t = threadIdx.x, blk = blockIdx.x;
    const int ch = t & 31, grp = t >> 5;   // 8 warps
    const int e0 = blk * 2048;
    float s = 0.f, s2 = 0.f;
    for (int i = grp; i < 2048; i += 8) {
        int ge  = e0 + i;
        int b   = ge >> 17;
        int e   = ge & (EPB - 1);
        int ctr = (b << 14) + (e >> 3);
        int nbr = (b << 14) + ei[b * 2 * EPB + EPB + e];
        float d = zb[nbr * 32 + ch] - zb[ctr * 32 + ch];
        s += d; s2 += d * d;
    }
    sh[t] = s; sh[256 + t] = s2;
    __syncthreads();
    if (t < 32) {
        float a = 0.f, b2 = 0.f;
#pragma unroll
        for (int g = 0; g < 8; g++) { a += sh[g * 32 + t]; b2 += sh[256 + g * 32 + t]; }
        part[t * 256 + blk]            = a;
        part[32 * 256 + t * 256 + blk] = b2;
    }
}

// ---------------- combine: x_out = act_a(za) + max_k act_b(zb[nbr_k](-zb)) --
__global__ void __launch_bounds__(256) combine_k(const float* __restrict__ za,
                                                 const float* __restrict__ zb,
                                                 const int* __restrict__ ei,
                                                 float* __restrict__ xo,
                                                 int cout, int diffMode) {
    const int t = threadIdx.x;
    const int npb  = 256 / cout;
    const int node = blockIdx.x * npb + t / cout;
    const int ch   = t & (cout - 1);
    const int b = node >> 14, n = node & (NPTS - 1);
    const int* nb = ei + b * 2 * EPB + EPB + n * KNN;
    const int boff = b << 14;

    const float sb = g_sb[ch], hb = g_hb[ch];
    const float zc = diffMode ? zb[node * cout + ch] : 0.f;
    float mx = -1e30f;
#pragma unroll
    for (int k = 0; k < KNN; k++) {
        int nn = boff + nb[k];
        float v = (zb[nn * cout + ch] - zc) * sb + hb;
        v = v > 0.f ? v : 0.2f * v;
        mx = fmaxf(mx, v);
    }
    float va = za[node * cout + ch] * g_sa[ch] + g_ha[ch];
    va = va > 0.f ? va : 0.2f * va;
    xo[node * cout + ch] = va + mx;
}

// ---------------- cat projection: zc[row] = concat(x0..x3)[row] . Wcat ------
// Also emits per-block stat partials: part[blk] (sum), part[8192+blk] (sumsq).
__global__ void __launch_bounds__(256) cat_k(const float* __restrict__ Wc,
                                             float* __restrict__ part) {
    __shared__ float sw[16];
    const int warp = threadIdx.x >> 5, lane = threadIdx.x & 31;
    const int row = blockIdx.x * 8 + warp;
    float s = 0.f;
#pragma unroll
    for (int i = 0; i < 15; i++) {        // 480 / 32
        int j = lane + i * 32;
        float v;
        if (j < 32)       v = g_x0[row * 32  + j];
        else if (j < 96)  v = g_x1[row * 64  + (j - 32)];
        else if (j < 224) v = g_x2[row * 128 + (j - 96)];
        else              v = g_x3[row * 256 + (j - 224)];
        s += v * Wc[j];
    }
#pragma unroll
    for (int o = 16; o; o >>= 1) s += __shfl_xor_sync(0xffffffffu, s, o);
    if (lane == 0) {
        g_zc[row] = s;
        sw[warp] = s;
        sw[8 + warp] = s * s;
    }
    __syncthreads();
    if (threadIdx.x == 0) {
        float a = 0.f, b = 0.f;
#pragma unroll
        for (int g = 0; g < 8; g++) { a += sw[g]; b += sw[8 + g]; }
        part[blockIdx.x]        = a;
        part[8192 + blockIdx.x] = b;
    }
}

// ---------------- final: BN(1ch) + lrelu + bias -----------------------------
__global__ void final_k(const float* __restrict__ bias, float* __restrict__ out) {
    int i = blockIdx.x * 256 + threadIdx.x;
    float v = g_zc[i] * g_sa[0] + g_ha[0];
    v = v > 0.f ? v : 0.2f * v;
    out[i] = v + bias[0];
}

// ---------------- host orchestration ----------------------------------------
extern "C" void kernel_launch(void* const* d_in, const int* in_sizes, int n_in,
                              void* d_out, int out_size) {
    const float* x   = (const float*)d_in[0];
    const int*   ei  = (const int*)d_in[1];
    const float* W0a = (const float*)d_in[2];
    const float* g0a = (const float*)d_in[3];
    const float* b0a = (const float*)d_in[4];
    const float* W0b = (const float*)d_in[5];
    const float* g0b = (const float*)d_in[6];
    const float* b0b = (const float*)d_in[7];
    const float* W1a = (const float*)d_in[8];
    const float* g1a = (const float*)d_in[9];
    const float* b1a = (const float*)d_in[10];
    const float* W1b = (const float*)d_in[11];
    const float* g1b = (const float*)d_in[12];
    const float* b1b = (const float*)d_in[13];
    const float* W2a = (const float*)d_in[14];
    const float* g2a = (const float*)d_in[15];
    const float* b2a = (const float*)d_in[16];
    const float* W2b = (const float*)d_in[17];
    const float* g2b = (const float*)d_in[18];
    const float* b2b = (const float*)d_in[19];
    const float* W3a = (const float*)d_in[20];
    const float* g3a = (const float*)d_in[21];
    const float* b3a = (const float*)d_in[22];
    const float* W3b = (const float*)d_in[23];
    const float* g3b = (const float*)d_in[24];
    const float* b3b = (const float*)d_in[25];
    const float* Wct = (const float*)d_in[26];
    const float* gct = (const float*)d_in[27];
    const float* bct = (const float*)d_in[28];
    const float* bia = (const float*)d_in[29];
    float* out = (float*)d_out;

    float *x0, *x1, *x2, *x3, *za, *zb, *zc, *pa, *pb, *sa, *ha, *sb, *hb;
    cudaGetSymbolAddress((void**)&x0, g_x0);
    cudaGetSymbolAddress((void**)&x1, g_x1);
    cudaGetSymbolAddress((void**)&x2, g_x2);
    cudaGetSymbolAddress((void**)&x3, g_x3);
    cudaGetSymbolAddress((void**)&za, g_za);
    cudaGetSymbolAddress((void**)&zb, g_zb);
    cudaGetSymbolAddress((void**)&zc, g_zc);
    cudaGetSymbolAddress((void**)&pa, g_pa);
    cudaGetSymbolAddress((void**)&pb, g_pb);
    cudaGetSymbolAddress((void**)&sa, g_sa);
    cudaGetSymbolAddress((void**)&ha, g_ha);
    cudaGetSymbolAddress((void**)&sb, g_sb);
    cudaGetSymbolAddress((void**)&hb, g_hb);

    const float invN = 1.0f / 65536.0f;
    const float invE = 1.0f / 524288.0f;

    // ---- layer 0: 8 -> 32 ----
    gemm_k<8, 32, true ><<<dim3(GRIDX, 1), 256>>>(x, W0a, za, pa);
    gemm_k<8, 32, false><<<dim3(GRIDX, 1), 256>>>(x, W0b, zb, nullptr);
    stats2p_k<<<32, 256>>>(pa, g0a, b0a, 32, GRIDX, invN, sa, ha);
    estats1_k<<<256, 256>>>(zb, ei, pb);
    stats2p_k<<<32, 256>>>(pb, g0b, b0b, 32, 256, invE, sb, hb);
    combine_k<<<ROWS * 32 / 256, 256>>>(za, zb, ei, x0, 32, 1);

    // ---- layer 1: 32 -> 64 ----
    gemm_k<32, 64, true><<<dim3(GRIDX, 1), 256>>>(x0, W1a, za, pa);
    gemm_k<32, 64, true><<<dim3(GRIDX, 1), 256>>>(x0, W1b, zb, pb);
    stats2p_k<<<64, 256>>>(pa, g1a, b1a, 64, GRIDX, invN, sa, ha);
    stats2p_k<<<64, 256>>>(pb, g1b, b1b, 64, GRIDX, invN, sb, hb);
    combine_k<<<ROWS * 64 / 256, 256>>>(za, zb, ei, x1, 64, 0);

    // ---- layer 2: 64 -> 128 ----
    gemm_k<64, 128, true><<<dim3(GRIDX, 1), 256>>>(x1, W2a, za, pa);
    gemm_k<64, 128, true><<<dim3(GRIDX, 1), 256>>>(x1, W2b, zb, pb);
    stats2p_k<<<128, 256>>>(pa, g2a, b2a, 128, GRIDX, invN, sa, ha);
    stats2p_k<<<128, 256>>>(pb, g2b, b2b, 128, GRIDX, invN, sb, hb);
    combine_k<<<ROWS * 128 / 256, 256>>>(za, zb, ei, x2, 128, 0);

    // ---- layer 3: 128 -> 256 ----
    gemm_k<128, 256, true><<<dim3(GRIDX, 2), 256>>>(x2, W3a, za, pa);
    gemm_k<128, 256, true><<<dim3(GRIDX, 2), 256>>>(x2, W3b, zb, pb);
    stats2p_k<<<256, 256>>>(pa, g3a, b3a, 256, GRIDX, invN, sa, ha);
    stats2p_k<<<256, 256>>>(pb, g3b, b3b, 256, GRIDX, invN, sb, hb);
    combine_k<<<ROWS * 256 / 256, 256>>>(za, zb, ei, x3, 256, 0);

    // ---- cat 480 -> 1, BN, lrelu, +bias ----
    cat_k<<<ROWS / 8, 256>>>(Wct, pa);
    stats2p_k<<<1, 256>>>(pa, gct, bct, 1, 8192, invN, sa, ha);
    final_k<<<ROWS / 256, 256>>>(bia, out);
}

// round 13
// speedup vs baseline: 1.3550x; 1.3550x over previous
#include <cuda_runtime.h>
#include <cstdint>

// Problem constants
#define ROWS  65536      // B*N rows
#define NPTS  16384      // N
#define EPB   131072     // E per batch (N*K)
#define KNN   8
#define GRIDX 512        // ROWS / 128 row-blocks per GEMM
#define EBLK  2048       // estats blocks

// ---------------- scratch (device globals; no allocation allowed) ----------
__device__ float g_x0[ROWS * 32];
__device__ float g_x1[ROWS * 64];
__device__ float g_x2[ROWS * 128];
__device__ float g_dot[ROWS * 4];         // per-layer cat-projection partials
__device__ float g_za[ROWS * 256];
__device__ float g_zb[ROWS * 256];
__device__ float g_zc[ROWS];
__device__ float g_pa[256 * GRIDX * 2];   // stat partials (branch a)
__device__ float g_pb[256 * GRIDX * 2];   // stat partials (branch b / edge)
__device__ float g_sa[256], g_ha[256];    // BN scale/shift branch a
__device__ float g_sb[256], g_hb[256];    // BN scale/shift branch b

// ---------------- f32x2 helpers --------------------------------------------
__device__ __forceinline__ unsigned long long pack_dup(float a) {
    unsigned long long r;
    unsigned int ab = __float_as_uint(a);
    asm("mov.b64 %0, {%1, %1};" : "=l"(r) : "r"(ab));
    return r;
}
__device__ __forceinline__ float f2lo(unsigned long long v) {
    return __uint_as_float((unsigned int)(v & 0xffffffffULL));
}
__device__ __forceinline__ float f2hi(unsigned long long v) {
    return __uint_as_float((unsigned int)(v >> 32));
}

// ---------------- dual-branch GEMM: Cx = A @ Wx for x in {a,b} --------------
// blockIdx.z selects branch. Conflict-free Ws LDS (col = tx*2 + 32*j).
// STATS: fused per-block column sum/sumsq partials.
template <int CIN, int COUT, bool STATS>
__global__ void __launch_bounds__(256) gemm2_k(const float* __restrict__ A,
                                               const float* __restrict__ Wa,
                                               const float* __restrict__ Wb,
                                               float* __restrict__ Ca,
                                               float* __restrict__ Cb,
                                               float* __restrict__ parta,
                                               float* __restrict__ partb) {
    constexpr int BM = 128;
    constexpr int BN = (COUT < 128) ? COUT : 128;
    constexpr int TM = 8;
    constexpr int TN = BN / 16;
    constexpr int NJ = TN / 2;
    constexpr int BK = 8;

    __shared__ float sh[BM * BK + BK * BN];
    float* As = sh;
    float* Ws = sh + BM * BK;

    const float* W   = blockIdx.z ? Wb : Wa;
    float*       C   = blockIdx.z ? Cb : Ca;
    float*       part = blockIdx.z ? partb : parta;

    const int t   = threadIdx.x;
    const int tx  = t & 15;
    const int ty  = t >> 4;
    const int row0 = blockIdx.x * BM;
    const int col0 = blockIdx.y * BN;

    unsigned long long acc[TM][NJ];
#pragma unroll
    for (int m = 0; m < TM; m++)
#pragma unroll
        for (int j = 0; j < NJ; j++) acc[m][j] = 0ULL;

    for (int k0 = 0; k0 < CIN; k0 += BK) {
#pragma unroll
        for (int idx = t; idx < BM * BK; idx += 256) {
            int r = idx >> 3, c = idx & 7;
            As[r * BK + c] = A[(row0 + r) * CIN + k0 + c];
        }
#pragma unroll
        for (int idx = t; idx < BK * BN; idx += 256) {
            int kr = idx / BN, c = idx % BN;
            Ws[kr * BN + c] = W[(k0 + kr) * COUT + col0 + c];
        }
        __syncthreads();

#pragma unroll
        for (int k = 0; k < BK; k++) {
            unsigned long long a2[TM];
#pragma unroll
            for (int m = 0; m < TM; m++)
                a2[m] = pack_dup(As[(ty * TM + m) * BK + k]);
            unsigned long long w2[NJ];
#pragma unroll
            for (int j = 0; j < NJ; j++)
                w2[j] = *reinterpret_cast<const unsigned long long*>(
                    &Ws[k * BN + tx * 2 + 32 * j]);
#pragma unroll
            for (int m = 0; m < TM; m++)
#pragma unroll
                for (int j = 0; j < NJ; j++)
                    asm("fma.rn.f32x2 %0, %1, %2, %0;"
                        : "+l"(acc[m][j]) : "l"(a2[m]), "l"(w2[j]));
        }
        __syncthreads();
    }

#pragma unroll
    for (int m = 0; m < TM; m++) {
        int r = row0 + ty * TM + m;
#pragma unroll
        for (int j = 0; j < NJ; j++)
            *reinterpret_cast<unsigned long long*>(
                &C[r * COUT + col0 + tx * 2 + 32 * j]) = acc[m][j];
    }

    if (STATS) {
        float* red = sh;   // 16*BN floats, fits in sh
#pragma unroll
        for (int j = 0; j < NJ; j++) {
            float s0 = 0.f, s1 = 0.f;
#pragma unroll
            for (int m = 0; m < TM; m++) { s0 += f2lo(acc[m][j]); s1 += f2hi(acc[m][j]); }
            red[ty * BN + tx * 2 + 32 * j]     = s0;
            red[ty * BN + tx * 2 + 32 * j + 1] = s1;
        }
        __syncthreads();
        if (t < BN) {
            float s = 0.f;
#pragma unroll
            for (int g = 0; g < 16; g++) s += red[g * BN + t];
            part[(col0 + t) * GRIDX + blockIdx.x] = s;
        }
        __syncthreads();
#pragma unroll
        for (int j = 0; j < NJ; j++) {
            float s0 = 0.f, s1 = 0.f;
#pragma unroll
            for (int m = 0; m < TM; m++) {
                float lo = f2lo(acc[m][j]), hi = f2hi(acc[m][j]);
                s0 += lo * lo; s1 += hi * hi;
            }
            red[ty * BN + tx * 2 + 32 * j]     = s0;
            red[ty * BN + tx * 2 + 32 * j + 1] = s1;
        }
        __syncthreads();
        if (t < BN) {
            float s = 0.f;
#pragma unroll
            for (int g = 0; g < 16; g++) s += red[g * BN + t];
            part[COUT * GRIDX + (col0 + t) * GRIDX + blockIdx.x] = s;
        }
    }
}

// ---------------- BN stats stage 2 (parallel): one block per channel --------
__global__ void __launch_bounds__(256) stats2p_k(const float* __restrict__ part,
                                                 const float* __restrict__ gam,
                                                 const float* __restrict__ bet,
                                                 int cout, int nblk, float invM,
                                                 float* __restrict__ scale,
                                                 float* __restrict__ shift) {
    const int ch = blockIdx.x, t = threadIdx.x;
    const float* ps = part + (size_t)ch * nblk;
    const float* pq = part + (size_t)cout * nblk + (size_t)ch * nblk;
    float s = 0.f, s2 = 0.f;
    for (int i = t; i < nblk; i += 256) { s += ps[i]; s2 += pq[i]; }
#pragma unroll
    for (int o = 16; o; o >>= 1) {
        s  += __shfl_xor_sync(0xffffffffu, s, o);
        s2 += __shfl_xor_sync(0xffffffffu, s2, o);
    }
    __shared__ float sw[16];
    int w = t >> 5, l = t & 31;
    if (l == 0) { sw[w] = s; sw[8 + w] = s2; }
    __syncthreads();
    if (t == 0) {
        float a = 0.f, b = 0.f;
#pragma unroll
        for (int g = 0; g < 8; g++) { a += sw[g]; b += sw[8 + g]; }
        float m = a * invM;
        float v = fmaxf(b * invM - m * m, 0.f);
        float sc = gam[ch] * rsqrtf(v + 1e-5f);
        scale[ch] = sc;
        shift[ch] = bet[ch] - m * sc;
    }
}

// ---------------- edge-level stats for layer-0 branch b ---------------------
// grid=EBLK blocks x 256 edges each (high occupancy, latency-hiding).
__global__ void __launch_bounds__(256) estats1_k(const float* __restrict__ zb,
                                                 const int* __restrict__ ei,
                                                 float* __restrict__ part) {
    __shared__ float sh[512];
    const int t = threadIdx.x, blk = blockIdx.x;
    const int ch = t & 31, grp = t >> 5;   // 8 warps
    const int e0 = blk * 256;
    float s = 0.f, s2 = 0.f;
#pragma unroll 4
    for (int i = grp; i < 256; i += 8) {
        int ge  = e0 + i;
        int b   = ge >> 17;
        int e   = ge & (EPB - 1);
        int ctr = (b << 14) + (e >> 3);
        int nbr = (b << 14) + ei[b * 2 * EPB + EPB + e];
        float d = zb[nbr * 32 + ch] - zb[ctr * 32 + ch];
        s += d; s2 += d * d;
    }
    sh[t] = s; sh[256 + t] = s2;
    __syncthreads();
    if (t < 32) {
        float a = 0.f, b2 = 0.f;
#pragma unroll
        for (int g = 0; g < 8; g++) { a += sh[g * 32 + t]; b2 += sh[256 + g * 32 + t]; }
        part[t * EBLK + blk]             = a;
        part[32 * EBLK + t * EBLK + blk] = b2;
    }
}

// ---------------- combine + fused cat-projection partial --------------------
// x_out = act_a(za) + max_k act_b(zb[nbr_k](-zb)); dot[node] = x_out . Wcseg
template <int COUT, bool WRITEX, bool DIFF>
__global__ void __launch_bounds__(256) combine_k(const float* __restrict__ za,
                                                 const float* __restrict__ zb,
                                                 const int* __restrict__ ei,
                                                 float* __restrict__ xo,
                                                 const float* __restrict__ Wc,
                                                 float* __restrict__ dot) {
    constexpr int NPB = 256 / COUT;
    constexpr int WPN = COUT / 32;
    const int t = threadIdx.x;
    const int node = blockIdx.x * NPB + t / COUT;
    const int ch   = t & (COUT - 1);
    const int b = node >> 14, n = node & (NPTS - 1);
    const int* nb = ei + b * 2 * EPB + EPB + n * KNN;
    const int boff = b << 14;

    const float sb = g_sb[ch], hb = g_hb[ch];
    const float zc = DIFF ? zb[node * COUT + ch] : 0.f;
    float mx = -1e30f;
#pragma unroll
    for (int k = 0; k < KNN; k++) {
        int nn = boff + nb[k];
        float v = (zb[nn * COUT + ch] - zc) * sb + hb;
        v = v > 0.f ? v : 0.2f * v;
        mx = fmaxf(mx, v);
    }
    float va = za[node * COUT + ch] * g_sa[ch] + g_ha[ch];
    va = va > 0.f ? va : 0.2f * va;
    float v = va + mx;
    if (WRITEX) xo[node * COUT + ch] = v;

    // fused cat-projection partial: block-local deterministic reduction
    float d = v * Wc[ch];
#pragma unroll
    for (int o = 16; o; o >>= 1) d += __shfl_xor_sync(0xffffffffu, d, o);
    __shared__ float sd[8];
    int w = t >> 5;
    if ((t & 31) == 0) sd[w] = d;
    __syncthreads();
    if (t < NPB) {
        float s = 0.f;
#pragma unroll
        for (int g = 0; g < WPN; g++) s += sd[t * WPN + g];
        dot[blockIdx.x * NPB + t] = s;
    }
}

// ---------------- zcat: zc = d0+d1+d2+d3, emit stat partials ----------------
__global__ void __launch_bounds__(256) zcat_k(float* __restrict__ part) {
    const int i = blockIdx.x * 256 + threadIdx.x;
    float s = g_dot[i] + g_dot[ROWS + i] + g_dot[2 * ROWS + i] + g_dot[3 * ROWS + i];
    g_zc[i] = s;
    float q = s * s;
#pragma unroll
    for (int o = 16; o; o >>= 1) {
        s += __shfl_xor_sync(0xffffffffu, s, o);
        q += __shfl_xor_sync(0xffffffffu, q, o);
    }
    __shared__ float sw[16];
    int w = threadIdx.x >> 5;
    if ((threadIdx.x & 31) == 0) { sw[w] = s; sw[8 + w] = q; }
    __syncthreads();
    if (threadIdx.x == 0) {
        float a = 0.f, b = 0.f;
#pragma unroll
        for (int g = 0; g < 8; g++) { a += sw[g]; b += sw[8 + g]; }
        part[blockIdx.x]       = a;
        part[256 + blockIdx.x] = b;
    }
}

// ---------------- final: BN(1ch) + lrelu + bias -----------------------------
__global__ void final_k(const float* __restrict__ bias, float* __restrict__ out) {
    int i = blockIdx.x * 256 + threadIdx.x;
    float v = g_zc[i] * g_sa[0] + g_ha[0];
    v = v > 0.f ? v : 0.2f * v;
    out[i] = v + bias[0];
}

// ---------------- host orchestration ----------------------------------------
extern "C" void kernel_launch(void* const* d_in, const int* in_sizes, int n_in,
                              void* d_out, int out_size) {
    const float* x   = (const float*)d_in[0];
    const int*   ei  = (const int*)d_in[1];
    const float* W0a = (const float*)d_in[2];
    const float* g0a = (const float*)d_in[3];
    const float* b0a = (const float*)d_in[4];
    const float* W0b = (const float*)d_in[5];
    const float* g0b = (const float*)d_in[6];
    const float* b0b = (const float*)d_in[7];
    const float* W1a = (const float*)d_in[8];
    const float* g1a = (const float*)d_in[9];
    const float* b1a = (const float*)d_in[10];
    const float* W1b = (const float*)d_in[11];
    const float* g1b = (const float*)d_in[12];
    const float* b1b = (const float*)d_in[13];
    const float* W2a = (const float*)d_in[14];
    const float* g2a = (const float*)d_in[15];
    const float* b2a = (const float*)d_in[16];
    const float* W2b = (const float*)d_in[17];
    const float* g2b = (const float*)d_in[18];
    const float* b2b = (const float*)d_in[19];
    const float* W3a = (const float*)d_in[20];
    const float* g3a = (const float*)d_in[21];
    const float* b3a = (const float*)d_in[22];
    const float* W3b = (const float*)d_in[23];
    const float* g3b = (const float*)d_in[24];
    const float* b3b = (const float*)d_in[25];
    const float* Wct = (const float*)d_in[26];
    const float* gct = (const float*)d_in[27];
    const float* bct = (const float*)d_in[28];
    const float* bia = (const float*)d_in[29];
    float* out = (float*)d_out;

    float *x0, *x1, *x2, *dt, *za, *zb, *pa, *pb, *sa, *ha, *sb, *hb;
    cudaGetSymbolAddress((void**)&x0, g_x0);
    cudaGetSymbolAddress((void**)&x1, g_x1);
    cudaGetSymbolAddress((void**)&x2, g_x2);
    cudaGetSymbolAddress((void**)&dt, g_dot);
    cudaGetSymbolAddress((void**)&za, g_za);
    cudaGetSymbolAddress((void**)&zb, g_zb);
    cudaGetSymbolAddress((void**)&pa, g_pa);
    cudaGetSymbolAddress((void**)&pb, g_pb);
    cudaGetSymbolAddress((void**)&sa, g_sa);
    cudaGetSymbolAddress((void**)&ha, g_ha);
    cudaGetSymbolAddress((void**)&sb, g_sb);
    cudaGetSymbolAddress((void**)&hb, g_hb);

    const float invN = 1.0f / 65536.0f;
    const float invE = 1.0f / 524288.0f;

    // ---- layer 0: 8 -> 32 ----
    gemm2_k<8, 32, true><<<dim3(GRIDX, 1, 2), 256>>>(x, W0a, W0b, za, zb, pa, pb);
    stats2p_k<<<32, 256>>>(pa, g0a, b0a, 32, GRIDX, invN, sa, ha);
    estats1_k<<<EBLK, 256>>>(zb, ei, pb);
    stats2p_k<<<32, 256>>>(pb, g0b, b0b, 32, EBLK, invE, sb, hb);
    combine_k<32, true, true><<<ROWS * 32 / 256, 256>>>(za, zb, ei, x0, Wct + 0, dt);

    // ---- layer 1: 32 -> 64 ----
    gemm2_k<32, 64, true><<<dim3(GRIDX, 1, 2), 256>>>(x0, W1a, W1b, za, zb, pa, pb);
    stats2p_k<<<64, 256>>>(pa, g1a, b1a, 64, GRIDX, invN, sa, ha);
    stats2p_k<<<64, 256>>>(pb, g1b, b1b, 64, GRIDX, invN, sb, hb);
    combine_k<64, true, false><<<ROWS * 64 / 256, 256>>>(za, zb, ei, x1, Wct + 32, dt + ROWS);

    // ---- layer 2: 64 -> 128 ----
    gemm2_k<64, 128, true><<<dim3(GRIDX, 1, 2), 256>>>(x1, W2a, W2b, za, zb, pa, pb);
    stats2p_k<<<128, 256>>>(pa, g2a, b2a, 128, GRIDX, invN, sa, ha);
    stats2p_k<<<128, 256>>>(pb, g2b, b2b, 128, GRIDX, invN, sb, hb);
    combine_k<128, true, false><<<ROWS * 128 / 256, 256>>>(za, zb, ei, x2, Wct + 96, dt + 2 * ROWS);

    // ---- layer 3: 128 -> 256 (x3 never materialized; only cat partials) ----
    gemm2_k<128, 256, true><<<dim3(GRIDX, 2, 2), 256>>>(x2, W3a, W3b, za, zb, pa, pb);
    stats2p_k<<<256, 256>>>(pa, g3a, b3a, 256, GRIDX, invN, sa, ha);
    stats2p_k<<<256, 256>>>(pb, g3b, b3b, 256, GRIDX, invN, sb, hb);
    combine_k<256, false, false><<<ROWS, 256>>>(za, zb, ei, nullptr, Wct + 224, dt + 3 * ROWS);

    // ---- cat sum, BN(1ch), lrelu, +bias ----
    zcat_k<<<256, 256>>>(pa);
    stats2p_k<<<1, 256>>>(pa, gct, bct, 1, 256, invN, sa, ha);
    final_k<<<ROWS / 256, 256>>>(bia, out);
}

// round 15
// speedup vs baseline: 1.8292x; 1.3500x over previous
#include <cuda_runtime.h>
#include <cuda_bf16.h>
#include <cstdint>

// Problem constants
#define ROWS  65536      // B*N rows
#define NPTS  16384      // N
#define EPB   131072     // E per batch (N*K)
#define KNN   8
#define GRIDX 512        // ROWS / 128 row-blocks per GEMM
#define EBLK  2048       // estats blocks

// ---------------- scratch (device globals; no allocation allowed) ----------
__device__ float g_x0[ROWS * 32];
__device__ __nv_bfloat16 g_x1h[ROWS * 64],  g_x1l[ROWS * 64];
__device__ __nv_bfloat16 g_x2h[ROWS * 128], g_x2l[ROWS * 128];
__device__ __nv_bfloat16 g_w2h[256 * 64],  g_w2l[256 * 64];    // [2*128 N, 64 K]
__device__ __nv_bfloat16 g_w3h[512 * 128], g_w3l[512 * 128];   // [2*256 N, 128 K]
__device__ float g_dot[ROWS * 4];
__device__ float g_za[ROWS * 256];
__device__ float g_zb[ROWS * 256];
__device__ float g_zc[ROWS];
__device__ float g_pa[256 * GRIDX * 2];
__device__ float g_pb[256 * GRIDX * 2];
__device__ float g_sa[256], g_ha[256];
__device__ float g_sb[256], g_hb[256];

// ---------------- helpers ----------------------------------------------------
__device__ __forceinline__ uint32_t smem_u32(const void* p) {
    uint32_t a;
    asm("{ .reg .u64 t; cvta.to.shared.u64 t, %1; cvt.u32.u64 %0, t; }" : "=r"(a) : "l"(p));
    return a;
}
__device__ __forceinline__ void ldsm4(uint32_t* r, uint32_t addr) {
    asm volatile("ldmatrix.sync.aligned.m8n8.x4.shared.b16 {%0,%1,%2,%3}, [%4];"
                 : "=r"(r[0]), "=r"(r[1]), "=r"(r[2]), "=r"(r[3]) : "r"(addr));
}
__device__ __forceinline__ void mma16816(float* d, const uint32_t* a, const uint32_t* b) {
    asm volatile(
        "mma.sync.aligned.m16n8k16.row.col.f32.bf16.bf16.f32 "
        "{%0,%1,%2,%3}, {%4,%5,%6,%7}, {%8,%9}, {%0,%1,%2,%3};"
        : "+f"(d[0]), "+f"(d[1]), "+f"(d[2]), "+f"(d[3])
        : "r"(a[0]), "r"(a[1]), "r"(a[2]), "r"(a[3]), "r"(b[0]), "r"(b[1]));
}

// ---------------- f32x2 helpers --------------------------------------------
__device__ __forceinline__ unsigned long long pack_dup(float a) {
    unsigned long long r;
    unsigned int ab = __float_as_uint(a);
    asm("mov.b64 %0, {%1, %1};" : "=l"(r) : "r"(ab));
    return r;
}
__device__ __forceinline__ float f2lo(unsigned long long v) {
    return __uint_as_float((unsigned int)(v & 0xffffffffULL));
}
__device__ __forceinline__ float f2hi(unsigned long long v) {
    return __uint_as_float((unsigned int)(v >> 32));
}

// ---------------- FFMA2 dual-branch GEMM (layers 0,1) ----------------------
template <int CIN, int COUT>
__global__ void __launch_bounds__(256) gemm2_k(const float* __restrict__ A,
                                               const float* __restrict__ Wa,
                                               const float* __restrict__ Wb,
                                               float* __restrict__ Ca,
                                               float* __restrict__ Cb,
                                               float* __restrict__ parta,
                                               float* __restrict__ partb) {
    constexpr int BM = 128;
    constexpr int BN = (COUT < 128) ? COUT : 128;
    constexpr int TM = 8;
    constexpr int TN = BN / 16;
    constexpr int NJ = TN / 2;
    constexpr int BK = 8;

    __shared__ float sh[BM * BK + BK * BN];
    float* As = sh;
    float* Ws = sh + BM * BK;

    const float* W    = blockIdx.z ? Wb : Wa;
    float*       C    = blockIdx.z ? Cb : Ca;
    float*       part = blockIdx.z ? partb : parta;

    const int t   = threadIdx.x;
    const int tx  = t & 15;
    const int ty  = t >> 4;
    const int row0 = blockIdx.x * BM;

    unsigned long long acc[TM][NJ];
#pragma unroll
    for (int m = 0; m < TM; m++)
#pragma unroll
        for (int j = 0; j < NJ; j++) acc[m][j] = 0ULL;

    for (int k0 = 0; k0 < CIN; k0 += BK) {
#pragma unroll
        for (int idx = t; idx < BM * BK; idx += 256) {
            int r = idx >> 3, c = idx & 7;
            As[r * BK + c] = A[(row0 + r) * CIN + k0 + c];
        }
#pragma unroll
        for (int idx = t; idx < BK * BN; idx += 256) {
            int kr = idx / BN, c = idx % BN;
            Ws[kr * BN + c] = W[(k0 + kr) * COUT + c];
        }
        __syncthreads();

#pragma unroll
        for (int k = 0; k < BK; k++) {
            unsigned long long a2[TM];
#pragma unroll
            for (int m = 0; m < TM; m++)
                a2[m] = pack_dup(As[(ty * TM + m) * BK + k]);
            unsigned long long w2[NJ];
#pragma unroll
            for (int j = 0; j < NJ; j++)
                w2[j] = *reinterpret_cast<const unsigned long long*>(
                    &Ws[k * BN + tx * 2 + 32 * j]);
#pragma unroll
            for (int m = 0; m < TM; m++)
#pragma unroll
                for (int j = 0; j < NJ; j++)
                    asm("fma.rn.f32x2 %0, %1, %2, %0;"
                        : "+l"(acc[m][j]) : "l"(a2[m]), "l"(w2[j]));
        }
        __syncthreads();
    }

#pragma unroll
    for (int m = 0; m < TM; m++) {
        int r = row0 + ty * TM + m;
#pragma unroll
        for (int j = 0; j < NJ; j++)
            *reinterpret_cast<unsigned long long*>(
                &C[r * COUT + tx * 2 + 32 * j]) = acc[m][j];
    }

    // fused stat partials
    float* red = sh;
#pragma unroll
    for (int j = 0; j < NJ; j++) {
        float s0 = 0.f, s1 = 0.f;
#pragma unroll
        for (int m = 0; m < TM; m++) { s0 += f2lo(acc[m][j]); s1 += f2hi(acc[m][j]); }
        red[ty * BN + tx * 2 + 32 * j]     = s0;
        red[ty * BN + tx * 2 + 32 * j + 1] = s1;
    }
    __syncthreads();
    if (t < BN) {
        float s = 0.f;
#pragma unroll
        for (int g = 0; g < 16; g++) s += red[g * BN + t];
        part[t * GRIDX + blockIdx.x] = s;
    }
    __syncthreads();
#pragma unroll
    for (int j = 0; j < NJ; j++) {
        float s0 = 0.f, s1 = 0.f;
#pragma unroll
        for (int m = 0; m < TM; m++) {
            float lo = f2lo(acc[m][j]), hi = f2hi(acc[m][j]);
            s0 += lo * lo; s1 += hi * hi;
        }
        red[ty * BN + tx * 2 + 32 * j]     = s0;
        red[ty * BN + tx * 2 + 32 * j + 1] = s1;
    }
    __syncthreads();
    if (t < BN) {
        float s = 0.f;
#pragma unroll
        for (int g = 0; g < 16; g++) s += red[g * BN + t];
        part[COUT * GRIDX + t * GRIDX + blockIdx.x] = s;
    }
}

// ---------------- mma.sync dual-branch GEMM (layers 2,3), bf16 split-2 ------
// C = Ahi@Whi + Ahi@Wlo + Alo@Whi, fp32 accum in registers (HMMA).
// A: [ROWS, CIN] bf16 hi/lo. W: [CHUNKS*128 (N rows), CIN] bf16 hi/lo (n-major).
// grid = (GRIDX row-blocks, CHUNKS); chunk c < CHUNKS/2 -> branch a, else b.
template <int CIN, int CHUNKS>
__global__ void __launch_bounds__(256) tgemm_k(
    const __nv_bfloat16* __restrict__ Ah, const __nv_bfloat16* __restrict__ Al,
    const __nv_bfloat16* __restrict__ Wh, const __nv_bfloat16* __restrict__ Wl,
    float* __restrict__ za, float* __restrict__ zb,
    float* __restrict__ pa, float* __restrict__ pb) {
    constexpr int NB = CHUNKS * 64;      // per-branch COUT
    constexpr int SA = CIN + 8;          // smem row stride (elems), +16B pad
    constexpr int KS = CIN / 16;
    constexpr int V  = CIN / 8;          // 16B vectors per row

    extern __shared__ __align__(16) char smem[];
    __nv_bfloat16* Ahs = (__nv_bfloat16*)smem;        // 128 x SA
    __nv_bfloat16* Als = Ahs + 128 * SA;
    __nv_bfloat16* Whs = Als + 128 * SA;
    __nv_bfloat16* Wls = Whs + 128 * SA;

    const int t = threadIdx.x, lane = t & 31, wid = t >> 5;
    const int wm = wid & 3, wn = wid >> 2;            // 4x2 warp grid
    const int rb = blockIdx.x;
    const int c  = blockIdx.y;
    const int br = (c >= CHUNKS / 2);
    const int gcb = (c - br * (CHUNKS / 2)) * 128;

    // ---- load A rows rb*128..+127 and W rows c*128..+127 ----
    {
        const size_t ab = (size_t)rb * 128 * CIN;
        const size_t wb = (size_t)c * 128 * CIN;
#pragma unroll
        for (int u = t; u < 128 * V; u += 256) {
            int row = u / V, k8 = (u % V) * 8;
            *(uint4*)&Ahs[row * SA + k8] = *(const uint4*)&Ah[ab + row * CIN + k8];
            *(uint4*)&Als[row * SA + k8] = *(const uint4*)&Al[ab + row * CIN + k8];
            *(uint4*)&Whs[row * SA + k8] = *(const uint4*)&Wh[wb + row * CIN + k8];
            *(uint4*)&Wls[row * SA + k8] = *(const uint4*)&Wl[wb + row * CIN + k8];
        }
    }
    __syncthreads();

    float acc[2][8][4];
#pragma unroll
    for (int mi = 0; mi < 2; mi++)
#pragma unroll
        for (int jn = 0; jn < 8; jn++)
#pragma unroll
            for (int q = 0; q < 4; q++) acc[mi][jn][q] = 0.f;

    const uint32_t sAh = smem_u32(Ahs), sAl = smem_u32(Als);
    const uint32_t sWh = smem_u32(Whs), sWl = smem_u32(Wls);

    for (int ks = 0; ks < KS; ks++) {
        uint32_t ah[2][4], al[2][4];
#pragma unroll
        for (int mi = 0; mi < 2; mi++) {
            int row = wm * 32 + mi * 16 + (lane & 15);
            uint32_t off = (uint32_t)((row * SA + ks * 16 + ((lane >> 4) << 3)) * 2);
            ldsm4(ah[mi], sAh + off);
            ldsm4(al[mi], sAl + off);
        }
#pragma unroll
        for (int bj = 0; bj < 4; bj++) {
            int rowb = wn * 64 + bj * 16 + ((lane >> 4) << 3) + (lane & 7);
            uint32_t koff = ((lane >> 3) & 1) * 8;
            uint32_t off = (uint32_t)((rowb * SA + ks * 16 + koff) * 2);
            uint32_t bh[4], bl[4];
            ldsm4(bh, sWh + off);
            ldsm4(bl, sWl + off);
#pragma unroll
            for (int mi = 0; mi < 2; mi++) {
                mma16816(acc[mi][2 * bj],     ah[mi], bh);
                mma16816(acc[mi][2 * bj + 1], ah[mi], bh + 2);
                mma16816(acc[mi][2 * bj],     ah[mi], bl);
                mma16816(acc[mi][2 * bj + 1], ah[mi], bl + 2);
                mma16816(acc[mi][2 * bj],     al[mi], bh);
                mma16816(acc[mi][2 * bj + 1], al[mi], bh + 2);
            }
        }
    }

    // ---- store C (float2 per frag pair; cols 2t,2t+1 contiguous) ----
    const int g = lane >> 2, tg = lane & 3;
    float* out = br ? zb : za;
#pragma unroll
    for (int mi = 0; mi < 2; mi++)
#pragma unroll
        for (int jn = 0; jn < 8; jn++) {
            int col = wn * 64 + jn * 8 + 2 * tg;
            int r0  = wm * 32 + mi * 16 + g;
            size_t base = ((size_t)rb * 128 + r0) * NB + gcb + col;
            float2 v0 = make_float2(acc[mi][jn][0], acc[mi][jn][1]);
            float2 v1 = make_float2(acc[mi][jn][2], acc[mi][jn][3]);
            *(float2*)&out[base]          = v0;
            *(float2*)&out[base + 8 * NB] = v1;
        }

    // ---- fused BN stat partials (reuse smem; col-major transpose) ----
    __syncthreads();
    float* statb = (float*)smem;   // [128 cols][132]
#pragma unroll
    for (int mi = 0; mi < 2; mi++)
#pragma unroll
        for (int jn = 0; jn < 8; jn++) {
            int col = wn * 64 + jn * 8 + 2 * tg;
            int r0  = wm * 32 + mi * 16 + g;
            statb[col * 132 + r0]           = acc[mi][jn][0];
            statb[(col + 1) * 132 + r0]     = acc[mi][jn][1];
            statb[col * 132 + r0 + 8]       = acc[mi][jn][2];
            statb[(col + 1) * 132 + r0 + 8] = acc[mi][jn][3];
        }
    __syncthreads();
    if (t < 128) {
        float* part = br ? pb : pa;
        float s = 0.f, s2 = 0.f;
#pragma unroll
        for (int rr = 0; rr < 128; rr += 4) {
            float4 v = *(float4*)&statb[t * 132 + rr];
            s  += v.x + v.y + v.z + v.w;
            s2 += v.x * v.x + v.y * v.y + v.z * v.z + v.w * v.w;
        }
        part[(gcb + t) * GRIDX + rb]              = s;
        part[NB * GRIDX + (gcb + t) * GRIDX + rb] = s2;
    }
}

// ---------------- weight transpose + bf16 split ----------------------------
__global__ void wsplit_k(const float* __restrict__ Wa, const float* __restrict__ Wb,
                         int cin, int cout,
                         __nv_bfloat16* __restrict__ th, __nv_bfloat16* __restrict__ tl) {
    int idx = blockIdx.x * 256 + threadIdx.x;
    if (idx >= 2 * cout * cin) return;
    int n = idx / cin, k = idx % cin;
    float v = (n < cout) ? Wa[k * cout + n] : Wb[k * cout + (n - cout)];
    __nv_bfloat16 h = __float2bfloat16(v);
    th[idx] = h;
    tl[idx] = __float2bfloat16(v - __bfloat162float(h));
}

// ---------------- BN stats stage 2 ------------------------------------------
__global__ void __launch_bounds__(256) stats2p_k(const float* __restrict__ part,
                                                 const float* __restrict__ gam,
                                                 const float* __restrict__ bet,
                                                 int cout, int nblk, float invM,
                                                 float* __restrict__ scale,
                                                 float* __restrict__ shift) {
    const int ch = blockIdx.x, t = threadIdx.x;
    const float* ps = part + (size_t)ch * nblk;
    const float* pq = part + (size_t)cout * nblk + (size_t)ch * nblk;
    float s = 0.f, s2 = 0.f;
    for (int i = t; i < nblk; i += 256) { s += ps[i]; s2 += pq[i]; }
#pragma unroll
    for (int o = 16; o; o >>= 1) {
        s  += __shfl_xor_sync(0xffffffffu, s, o);
        s2 += __shfl_xor_sync(0xffffffffu, s2, o);
    }
    __shared__ float sw[16];
    int w = t >> 5, l = t & 31;
    if (l == 0) { sw[w] = s; sw[8 + w] = s2; }
    __syncthreads();
    if (t == 0) {
        float a = 0.f, b = 0.f;
#pragma unroll
        for (int g = 0; g < 8; g++) { a += sw[g]; b += sw[8 + g]; }
        float m = a * invM;
        float v = fmaxf(b * invM - m * m, 0.f);
        float sc = gam[ch] * rsqrtf(v + 1e-5f);
        scale[ch] = sc;
        shift[ch] = bet[ch] - m * sc;
    }
}

// ---------------- edge-level stats (layer-0 branch b) ------------------------
__global__ void __launch_bounds__(256) estats1_k(const float* __restrict__ zb,
                                                 const int* __restrict__ ei,
                                                 float* __restrict__ part) {
    __shared__ float sh[512];
    const int t = threadIdx.x, blk = blockIdx.x;
    const int ch = t & 31, grp = t >> 5;
    const int e0 = blk * 256;
    float s = 0.f, s2 = 0.f;
#pragma unroll 4
    for (int i = grp; i < 256; i += 8) {
        int ge  = e0 + i;
        int b   = ge >> 17;
        int e   = ge & (EPB - 1);
        int ctr = (b << 14) + (e >> 3);
        int nbr = (b << 14) + ei[b * 2 * EPB + EPB + e];
        float d = zb[nbr * 32 + ch] - zb[ctr * 32 + ch];
        s += d; s2 += d * d;
    }
    sh[t] = s; sh[256 + t] = s2;
    __syncthreads();
    if (t < 32) {
        float a = 0.f, b2 = 0.f;
#pragma unroll
        for (int g = 0; g < 8; g++) { a += sh[g * 32 + t]; b2 += sh[256 + g * 32 + t]; }
        part[t * EBLK + blk]             = a;
        part[32 * EBLK + t * EBLK + blk] = b2;
    }
}

// ---------------- combine + fused cat-projection partial --------------------
template <int COUT, bool DIFF, bool WRITEF, bool WRITEH>
__global__ void __launch_bounds__(256) combine_k(const float* __restrict__ za,
                                                 const float* __restrict__ zb,
                                                 const int* __restrict__ ei,
                                                 float* __restrict__ xo,
                                                 __nv_bfloat16* __restrict__ xh,
                                                 __nv_bfloat16* __restrict__ xl,
                                                 const float* __restrict__ Wc,
                                                 float* __restrict__ dot) {
    constexpr int NPB = 256 / COUT;
    constexpr int WPN = COUT / 32;
    const int t = threadIdx.x;
    const int node = blockIdx.x * NPB + t / COUT;
    const int ch   = t & (COUT - 1);
    const int b = node >> 14, n = node & (NPTS - 1);
    const int* nb = ei + b * 2 * EPB + EPB + n * KNN;
    const int boff = b << 14;

    const float sb = g_sb[ch], hb = g_hb[ch];
    const float zc = DIFF ? zb[node * COUT + ch] : 0.f;
    float mx = -1e30f;
#pragma unroll
    for (int k = 0; k < KNN; k++) {
        int nn = boff + nb[k];
        float v = (zb[nn * COUT + ch] - zc) * sb + hb;
        v = v > 0.f ? v : 0.2f * v;
        mx = fmaxf(mx, v);
    }
    float va = za[node * COUT + ch] * g_sa[ch] + g_ha[ch];
    va = va > 0.f ? va : 0.2f * va;
    float v = va + mx;
    if (WRITEF) xo[node * COUT + ch] = v;
    if (WRITEH) {
        __nv_bfloat16 h = __float2bfloat16(v);
        xh[node * COUT + ch] = h;
        xl[node * COUT + ch] = __float2bfloat16(v - __bfloat162float(h));
    }

    float d = v * Wc[ch];
#pragma unroll
    for (int o = 16; o; o >>= 1) d += __shfl_xor_sync(0xffffffffu, d, o);
    __shared__ float sd[8];
    int w = t >> 5;
    if ((t & 31) == 0) sd[w] = d;
    __syncthreads();
    if (t < NPB) {
        float s = 0.f;
#pragma unroll
        for (int g = 0; g < WPN; g++) s += sd[t * WPN + g];
        dot[blockIdx.x * NPB + t] = s;
    }
}

// ---------------- zcat + final ----------------------------------------------
__global__ void __launch_bounds__(256) zcat_k(float* __restrict__ part) {
    const int i = blockIdx.x * 256 + threadIdx.x;
    float s = g_dot[i] + g_dot[ROWS + i] + g_dot[2 * ROWS + i] + g_dot[3 * ROWS + i];
    g_zc[i] = s;
    float q = s * s;
#pragma unroll
    for (int o = 16; o; o >>= 1) {
        s += __shfl_xor_sync(0xffffffffu, s, o);
        q += __shfl_xor_sync(0xffffffffu, q, o);
    }
    __shared__ float sw[16];
    int w = threadIdx.x >> 5;
    if ((threadIdx.x & 31) == 0) { sw[w] = s; sw[8 + w] = q; }
    __syncthreads();
    if (threadIdx.x == 0) {
        float a = 0.f, b = 0.f;
#pragma unroll
        for (int g = 0; g < 8; g++) { a += sw[g]; b += sw[8 + g]; }
        part[blockIdx.x]       = a;
        part[256 + blockIdx.x] = b;
    }
}

__global__ void final_k(const float* __restrict__ bias, float* __restrict__ out) {
    int i = blockIdx.x * 256 + threadIdx.x;
    float v = g_zc[i] * g_sa[0] + g_ha[0];
    v = v > 0.f ? v : 0.2f * v;
    out[i] = v + bias[0];
}

// ---------------- host orchestration ----------------------------------------
extern "C" void kernel_launch(void* const* d_in, const int* in_sizes, int n_in,
                              void* d_out, int out_size) {
    const float* x   = (const float*)d_in[0];
    const int*   ei  = (const int*)d_in[1];
    const float* W0a = (const float*)d_in[2];
    const float* g0a = (const float*)d_in[3];
    const float* b0a = (const float*)d_in[4];
    const float* W0b = (const float*)d_in[5];
    const float* g0b = (const float*)d_in[6];
    const float* b0b = (const float*)d_in[7];
    const float* W1a = (const float*)d_in[8];
    const float* g1a = (const float*)d_in[9];
    const float* b1a = (const float*)d_in[10];
    const float* W1b = (const float*)d_in[11];
    const float* g1b = (const float*)d_in[12];
    const float* b1b = (const float*)d_in[13];
    const float* W2a = (const float*)d_in[14];
    const float* g2a = (const float*)d_in[15];
    const float* b2a = (const float*)d_in[16];
    const float* W2b = (const float*)d_in[17];
    const float* g2b = (const float*)d_in[18];
    const float* b2b = (const float*)d_in[19];
    const float* W3a = (const float*)d_in[20];
    const float* g3a = (const float*)d_in[21];
    const float* b3a = (const float*)d_in[22];
    const float* W3b = (const float*)d_in[23];
    const float* g3b = (const float*)d_in[24];
    const float* b3b = (const float*)d_in[25];
    const float* Wct = (const float*)d_in[26];
    const float* gct = (const float*)d_in[27];
    const float* bct = (const float*)d_in[28];
    const float* bia = (const float*)d_in[29];
    float* out = (float*)d_out;

    float *x0, *dt, *za, *zb, *pa, *pb, *sa, *ha, *sb, *hb;
    __nv_bfloat16 *x1h, *x1l, *x2h, *x2l, *w2h, *w2l, *w3h, *w3l;
    cudaGetSymbolAddress((void**)&x0, g_x0);
    cudaGetSymbolAddress((void**)&dt, g_dot);
    cudaGetSymbolAddress((void**)&za, g_za);
    cudaGetSymbolAddress((void**)&zb, g_zb);
    cudaGetSymbolAddress((void**)&pa, g_pa);
    cudaGetSymbolAddress((void**)&pb, g_pb);
    cudaGetSymbolAddress((void**)&sa, g_sa);
    cudaGetSymbolAddress((void**)&ha, g_ha);
    cudaGetSymbolAddress((void**)&sb, g_sb);
    cudaGetSymbolAddress((void**)&hb, g_hb);
    cudaGetSymbolAddress((void**)&x1h, g_x1h);
    cudaGetSymbolAddress((void**)&x1l, g_x1l);
    cudaGetSymbolAddress((void**)&x2h, g_x2h);
    cudaGetSymbolAddress((void**)&x2l, g_x2l);
    cudaGetSymbolAddress((void**)&w2h, g_w2h);
    cudaGetSymbolAddress((void**)&w2l, g_w2l);
    cudaGetSymbolAddress((void**)&w3h, g_w3h);
    cudaGetSymbolAddress((void**)&w3l, g_w3l);

    const float invN = 1.0f / 65536.0f;
    const float invE = 1.0f / 524288.0f;

    const int smem2 = 4 * 128 * (64 + 8) * 2;    // 73728 B
    const int smem3 = 4 * 128 * (128 + 8) * 2;   // 139264 B
    cudaFuncSetAttribute((const void*)tgemm_k<64, 2>,
                         cudaFuncAttributeMaxDynamicSharedMemorySize, smem2);
    cudaFuncSetAttribute((const void*)tgemm_k<128, 4>,
                         cudaFuncAttributeMaxDynamicSharedMemorySize, smem3);

    // ---- weight prep (independent) ----
    wsplit_k<<<(2 * 128 * 64 + 255) / 256, 256>>>(W2a, W2b, 64, 128, w2h, w2l);
    wsplit_k<<<(2 * 256 * 128 + 255) / 256, 256>>>(W3a, W3b, 128, 256, w3h, w3l);

    // ---- layer 0: 8 -> 32 (FFMA2) ----
    gemm2_k<8, 32><<<dim3(GRIDX, 1, 2), 256>>>(x, W0a, W0b, za, zb, pa, pb);
    stats2p_k<<<32, 256>>>(pa, g0a, b0a, 32, GRIDX, invN, sa, ha);
    estats1_k<<<EBLK, 256>>>(zb, ei, pb);
    stats2p_k<<<32, 256>>>(pb, g0b, b0b, 32, EBLK, invE, sb, hb);
    combine_k<32, true, true, false><<<ROWS * 32 / 256, 256>>>(
        za, zb, ei, x0, nullptr, nullptr, Wct + 0, dt);

    // ---- layer 1: 32 -> 64 (FFMA2) ----
    gemm2_k<32, 64><<<dim3(GRIDX, 1, 2), 256>>>(x0, W1a, W1b, za, zb, pa, pb);
    stats2p_k<<<64, 256>>>(pa, g1a, b1a, 64, GRIDX, invN, sa, ha);
    stats2p_k<<<64, 256>>>(pb, g1b, b1b, 64, GRIDX, invN, sb, hb);
    combine_k<64, false, false, true><<<ROWS * 64 / 256, 256>>>(
        za, zb, ei, nullptr, x1h, x1l, Wct + 32, dt + ROWS);

    // ---- layer 2: 64 -> 128 (mma.sync bf16 split) ----
    tgemm_k<64, 2><<<dim3(GRIDX, 2), 256, smem2>>>(x1h, x1l, w2h, w2l, za, zb, pa, pb);
    stats2p_k<<<128, 256>>>(pa, g2a, b2a, 128, GRIDX, invN, sa, ha);
    stats2p_k<<<128, 256>>>(pb, g2b, b2b, 128, GRIDX, invN, sb, hb);
    combine_k<128, false, false, true><<<ROWS * 128 / 256, 256>>>(
        za, zb, ei, nullptr, x2h, x2l, Wct + 96, dt + 2 * ROWS);

    // ---- layer 3: 128 -> 256 (mma.sync bf16 split; x3 never materialized) ----
    tgemm_k<128, 4><<<dim3(GRIDX, 4), 256, smem3>>>(x2h, x2l, w3h, w3l, za, zb, pa, pb);
    stats2p_k<<<256, 256>>>(pa, g3a, b3a, 256, GRIDX, invN, sa, ha);
    stats2p_k<<<256, 256>>>(pb, g3b, b3b, 256, GRIDX, invN, sb, hb);
    combine_k<256, false, false, false><<<ROWS, 256>>>(
        za, zb, ei, nullptr, nullptr, nullptr, Wct + 224, dt + 3 * ROWS);

    // ---- cat sum, BN(1ch), lrelu, +bias ----
    zcat_k<<<256, 256>>>(pa);
    stats2p_k<<<1, 256>>>(pa, gct, bct, 1, 256, invN, sa, ha);
    final_k<<<ROWS / 256, 256>>>(bia, out);
}

// round 16
// speedup vs baseline: 1.8800x; 1.0278x over previous
#include <cuda_runtime.h>
#include <cuda_bf16.h>
#include <cstdint>

// Problem constants
#define ROWS  65536      // B*N rows
#define NPTS  16384      // N
#define EPB   131072     // E per batch (N*K)
#define KNN   8
#define GRIDX 512        // ROWS / 128 row-blocks per GEMM
#define EBLK  2048       // estats blocks

// ---------------- scratch (device globals; no allocation allowed) ----------
__device__ __nv_bfloat16 g_x0h[ROWS * 32],  g_x0l[ROWS * 32];
__device__ __nv_bfloat16 g_x1h[ROWS * 64],  g_x1l[ROWS * 64];
__device__ __nv_bfloat16 g_x2h[ROWS * 128], g_x2l[ROWS * 128];
__device__ __nv_bfloat16 g_w1h[128 * 32],  g_w1l[128 * 32];    // [2*64 N, 32 K]
__device__ __nv_bfloat16 g_w2h[256 * 64],  g_w2l[256 * 64];    // [2*128 N, 64 K]
__device__ __nv_bfloat16 g_w3h[512 * 128], g_w3l[512 * 128];   // [2*256 N, 128 K]
__device__ float g_dot[ROWS * 4];
__device__ float g_za[ROWS * 256];
__device__ float g_zb[ROWS * 256];
__device__ float g_zc[ROWS];
__device__ float g_pa[256 * GRIDX * 2];
__device__ float g_pb[256 * GRIDX * 2];
__device__ float g_sa[256], g_ha[256];
__device__ float g_sb[256], g_hb[256];

// ---------------- helpers ----------------------------------------------------
__device__ __forceinline__ uint32_t smem_u32(const void* p) {
    uint32_t a;
    asm("{ .reg .u64 t; cvta.to.shared.u64 t, %1; cvt.u32.u64 %0, t; }" : "=r"(a) : "l"(p));
    return a;
}
__device__ __forceinline__ void ldsm4(uint32_t* r, uint32_t addr) {
    asm volatile("ldmatrix.sync.aligned.m8n8.x4.shared.b16 {%0,%1,%2,%3}, [%4];"
                 : "=r"(r[0]), "=r"(r[1]), "=r"(r[2]), "=r"(r[3]) : "r"(addr));
}
__device__ __forceinline__ void mma16816(float* d, const uint32_t* a, const uint32_t* b) {
    asm volatile(
        "mma.sync.aligned.m16n8k16.row.col.f32.bf16.bf16.f32 "
        "{%0,%1,%2,%3}, {%4,%5,%6,%7}, {%8,%9}, {%0,%1,%2,%3};"
        : "+f"(d[0]), "+f"(d[1]), "+f"(d[2]), "+f"(d[3])
        : "r"(a[0]), "r"(a[1]), "r"(a[2]), "r"(a[3]), "r"(b[0]), "r"(b[1]));
}

// ---------------- f32x2 helpers --------------------------------------------
__device__ __forceinline__ unsigned long long pack_dup(float a) {
    unsigned long long r;
    unsigned int ab = __float_as_uint(a);
    asm("mov.b64 %0, {%1, %1};" : "=l"(r) : "r"(ab));
    return r;
}
__device__ __forceinline__ float f2lo(unsigned long long v) {
    return __uint_as_float((unsigned int)(v & 0xffffffffULL));
}
__device__ __forceinline__ float f2hi(unsigned long long v) {
    return __uint_as_float((unsigned int)(v >> 32));
}

// ---------------- FFMA2 dual-branch GEMM (layer 0 only) ---------------------
template <int CIN, int COUT>
__global__ void __launch_bounds__(256) gemm2_k(const float* __restrict__ A,
                                               const float* __restrict__ Wa,
                                               const float* __restrict__ Wb,
                                               float* __restrict__ Ca,
                                               float* __restrict__ Cb,
                                               float* __restrict__ parta,
                                               float* __restrict__ partb) {
    constexpr int BM = 128;
    constexpr int BN = (COUT < 128) ? COUT : 128;
    constexpr int TM = 8;
    constexpr int TN = BN / 16;
    constexpr int NJ = TN / 2;
    constexpr int BK = 8;

    __shared__ float sh[BM * BK + BK * BN];
    float* As = sh;
    float* Ws = sh + BM * BK;

    const float* W    = blockIdx.z ? Wb : Wa;
    float*       C    = blockIdx.z ? Cb : Ca;
    float*       part = blockIdx.z ? partb : parta;

    const int t   = threadIdx.x;
    const int tx  = t & 15;
    const int ty  = t >> 4;
    const int row0 = blockIdx.x * BM;

    unsigned long long acc[TM][NJ];
#pragma unroll
    for (int m = 0; m < TM; m++)
#pragma unroll
        for (int j = 0; j < NJ; j++) acc[m][j] = 0ULL;

    for (int k0 = 0; k0 < CIN; k0 += BK) {
#pragma unroll
        for (int idx = t; idx < BM * BK; idx += 256) {
            int r = idx >> 3, c = idx & 7;
            As[r * BK + c] = A[(row0 + r) * CIN + k0 + c];
        }
#pragma unroll
        for (int idx = t; idx < BK * BN; idx += 256) {
            int kr = idx / BN, c = idx % BN;
            Ws[kr * BN + c] = W[(k0 + kr) * COUT + c];
        }
        __syncthreads();

#pragma unroll
        for (int k = 0; k < BK; k++) {
            unsigned long long a2[TM];
#pragma unroll
            for (int m = 0; m < TM; m++)
                a2[m] = pack_dup(As[(ty * TM + m) * BK + k]);
            unsigned long long w2[NJ];
#pragma unroll
            for (int j = 0; j < NJ; j++)
                w2[j] = *reinterpret_cast<const unsigned long long*>(
                    &Ws[k * BN + tx * 2 + 32 * j]);
#pragma unroll
            for (int m = 0; m < TM; m++)
#pragma unroll
                for (int j = 0; j < NJ; j++)
                    asm("fma.rn.f32x2 %0, %1, %2, %0;"
                        : "+l"(acc[m][j]) : "l"(a2[m]), "l"(w2[j]));
        }
        __syncthreads();
    }

#pragma unroll
    for (int m = 0; m < TM; m++) {
        int r = row0 + ty * TM + m;
#pragma unroll
        for (int j = 0; j < NJ; j++)
            *reinterpret_cast<unsigned long long*>(
                &C[r * COUT + tx * 2 + 32 * j]) = acc[m][j];
    }

    // fused stat partials
    float* red = sh;
#pragma unroll
    for (int j = 0; j < NJ; j++) {
        float s0 = 0.f, s1 = 0.f;
#pragma unroll
        for (int m = 0; m < TM; m++) { s0 += f2lo(acc[m][j]); s1 += f2hi(acc[m][j]); }
        red[ty * BN + tx * 2 + 32 * j]     = s0;
        red[ty * BN + tx * 2 + 32 * j + 1] = s1;
    }
    __syncthreads();
    if (t < BN) {
        float s = 0.f;
#pragma unroll
        for (int g = 0; g < 16; g++) s += red[g * BN + t];
        part[t * GRIDX + blockIdx.x] = s;
    }
    __syncthreads();
#pragma unroll
    for (int j = 0; j < NJ; j++) {
        float s0 = 0.f, s1 = 0.f;
#pragma unroll
        for (int m = 0; m < TM; m++) {
            float lo = f2lo(acc[m][j]), hi = f2hi(acc[m][j]);
            s0 += lo * lo; s1 += hi * hi;
        }
        red[ty * BN + tx * 2 + 32 * j]     = s0;
        red[ty * BN + tx * 2 + 32 * j + 1] = s1;
    }
    __syncthreads();
    if (t < BN) {
        float s = 0.f;
#pragma unroll
        for (int g = 0; g < 16; g++) s += red[g * BN + t];
        part[COUT * GRIDX + t * GRIDX + blockIdx.x] = s;
    }
}

// ---------------- mma.sync dual-branch GEMM (layers 1,2,3), bf16 split-2 ----
// C = Ahi@Whi + Ahi@Wlo + Alo@Whi, fp32 accum (HMMA).
// Normal: grid=(GRIDX, CHUNKS); chunk c < CHUNKS/2 -> branch a, else b.
// SPLITCOL (CHUNKS==1): one 128-col tile; cols 0-63 -> branch a, 64-127 -> b.
template <int CIN, int CHUNKS, bool SPLITCOL>
__global__ void __launch_bounds__(256) tgemm_k(
    const __nv_bfloat16* __restrict__ Ah, const __nv_bfloat16* __restrict__ Al,
    const __nv_bfloat16* __restrict__ Wh, const __nv_bfloat16* __restrict__ Wl,
    float* __restrict__ za, float* __restrict__ zb,
    float* __restrict__ pa, float* __restrict__ pb) {
    constexpr int NBB = SPLITCOL ? 64 : CHUNKS * 64;  // per-branch COUT
    constexpr int SA = CIN + 8;          // smem row stride (elems), +16B pad
    constexpr int KS = CIN / 16;
    constexpr int V  = CIN / 8;          // 16B vectors per row

    extern __shared__ __align__(16) char smem[];
    __nv_bfloat16* Ahs = (__nv_bfloat16*)smem;        // 128 x SA
    __nv_bfloat16* Als = Ahs + 128 * SA;
    __nv_bfloat16* Whs = Als + 128 * SA;
    __nv_bfloat16* Wls = Whs + 128 * SA;

    const int t = threadIdx.x, lane = t & 31, wid = t >> 5;
    const int wm = wid & 3, wn = wid >> 2;            // 4x2 warp grid
    const int rb = blockIdx.x;
    const int c  = blockIdx.y;
    const int br  = SPLITCOL ? 0 : (c >= CHUNKS / 2);
    const int gcb = SPLITCOL ? 0 : (c - br * (CHUNKS / 2)) * 128;

    // ---- load A rows rb*128..+127 and W rows c*128..+127 ----
    {
        const size_t ab = (size_t)rb * 128 * CIN;
        const size_t wb = (size_t)c * 128 * CIN;
#pragma unroll
        for (int u = t; u < 128 * V; u += 256) {
            int row = u / V, k8 = (u % V) * 8;
            *(uint4*)&Ahs[row * SA + k8] = *(const uint4*)&Ah[ab + row * CIN + k8];
            *(uint4*)&Als[row * SA + k8] = *(const uint4*)&Al[ab + row * CIN + k8];
            *(uint4*)&Whs[row * SA + k8] = *(const uint4*)&Wh[wb + row * CIN + k8];
            *(uint4*)&Wls[row * SA + k8] = *(const uint4*)&Wl[wb + row * CIN + k8];
        }
    }
    __syncthreads();

    float acc[2][8][4];
#pragma unroll
    for (int mi = 0; mi < 2; mi++)
#pragma unroll
        for (int jn = 0; jn < 8; jn++)
#pragma unroll
            for (int q = 0; q < 4; q++) acc[mi][jn][q] = 0.f;

    const uint32_t sAh = smem_u32(Ahs), sAl = smem_u32(Als);
    const uint32_t sWh = smem_u32(Whs), sWl = smem_u32(Wls);

    for (int ks = 0; ks < KS; ks++) {
        uint32_t ah[2][4], al[2][4];
#pragma unroll
        for (int mi = 0; mi < 2; mi++) {
            int row = wm * 32 + mi * 16 + (lane & 15);
            uint32_t off = (uint32_t)((row * SA + ks * 16 + ((lane >> 4) << 3)) * 2);
            ldsm4(ah[mi], sAh + off);
            ldsm4(al[mi], sAl + off);
        }
#pragma unroll
        for (int bj = 0; bj < 4; bj++) {
            int rowb = wn * 64 + bj * 16 + ((lane >> 4) << 3) + (lane & 7);
            uint32_t koff = ((lane >> 3) & 1) * 8;
            uint32_t off = (uint32_t)((rowb * SA + ks * 16 + koff) * 2);
            uint32_t bh[4], bl[4];
            ldsm4(bh, sWh + off);
            ldsm4(bl, sWl + off);
#pragma unroll
            for (int mi = 0; mi < 2; mi++) {
                mma16816(acc[mi][2 * bj],     ah[mi], bh);
                mma16816(acc[mi][2 * bj + 1], ah[mi], bh + 2);
                mma16816(acc[mi][2 * bj],     ah[mi], bl);
                mma16816(acc[mi][2 * bj + 1], ah[mi], bl + 2);
                mma16816(acc[mi][2 * bj],     al[mi], bh);
                mma16816(acc[mi][2 * bj + 1], al[mi], bh + 2);
            }
        }
    }

    // ---- store C (float2 per frag pair; cols 2t,2t+1 contiguous) ----
    const int g = lane >> 2, tg = lane & 3;
    {
        const int brS  = SPLITCOL ? wn : br;          // SPLITCOL: warp col half
        float* out = brS ? zb : za;
#pragma unroll
        for (int mi = 0; mi < 2; mi++)
#pragma unroll
            for (int jn = 0; jn < 8; jn++) {
                int col = SPLITCOL ? (jn * 8 + 2 * tg) : (wn * 64 + jn * 8 + 2 * tg);
                int r0  = wm * 32 + mi * 16 + g;
                size_t base = ((size_t)rb * 128 + r0) * NBB + gcb + col;
                float2 v0 = make_float2(acc[mi][jn][0], acc[mi][jn][1]);
                float2 v1 = make_float2(acc[mi][jn][2], acc[mi][jn][3]);
                *(float2*)&out[base]           = v0;
                *(float2*)&out[base + 8 * NBB] = v1;
            }
    }

    // ---- fused BN stat partials (reuse smem; col-major transpose) ----
    __syncthreads();
    float* statb = (float*)smem;   // [128 tile-cols][132]
#pragma unroll
    for (int mi = 0; mi < 2; mi++)
#pragma unroll
        for (int jn = 0; jn < 8; jn++) {
            int col = wn * 64 + jn * 8 + 2 * tg;
            int r0  = wm * 32 + mi * 16 + g;
            statb[col * 132 + r0]           = acc[mi][jn][0];
            statb[(col + 1) * 132 + r0]     = acc[mi][jn][1];
            statb[col * 132 + r0 + 8]       = acc[mi][jn][2];
            statb[(col + 1) * 132 + r0 + 8] = acc[mi][jn][3];
        }
    __syncthreads();
    if (t < 128) {
        const int brS = SPLITCOL ? (t >= 64) : br;
        const int ch  = SPLITCOL ? (t & 63) : (gcb + t);
        float* part = brS ? pb : pa;
        float s = 0.f, s2 = 0.f;
#pragma unroll
        for (int rr = 0; rr < 128; rr += 4) {
            float4 v = *(float4*)&statb[t * 132 + rr];
            s  += v.x + v.y + v.z + v.w;
            s2 += v.x * v.x + v.y * v.y + v.z * v.z + v.w * v.w;
        }
        part[ch * GRIDX + rb]               = s;
        part[NBB * GRIDX + ch * GRIDX + rb] = s2;
    }
}

// ---------------- weight transpose + bf16 split ----------------------------
__global__ void wsplit_k(const float* __restrict__ Wa, const float* __restrict__ Wb,
                         int cin, int cout,
                         __nv_bfloat16* __restrict__ th, __nv_bfloat16* __restrict__ tl) {
    int idx = blockIdx.x * 256 + threadIdx.x;
    if (idx >= 2 * cout * cin) return;
    int n = idx / cin, k = idx % cin;
    float v = (n < cout) ? Wa[k * cout + n] : Wb[k * cout + (n - cout)];
    __nv_bfloat16 h = __float2bfloat16(v);
    th[idx] = h;
    tl[idx] = __float2bfloat16(v - __bfloat162float(h));
}

// ---------------- BN stats stage 2: both branches in one launch -------------
// grid=(cout, 2): blockIdx.y selects branch params.
__global__ void __launch_bounds__(256) stats2d_k(const float* __restrict__ parta,
                                                 const float* __restrict__ partb,
                                                 const float* __restrict__ gama,
                                                 const float* __restrict__ beta,
                                                 const float* __restrict__ gamb,
                                                 const float* __restrict__ betb,
                                                 int cout, int nblka, int nblkb,
                                                 float invMa, float invMb) {
    const int ch = blockIdx.x, t = threadIdx.x, brn = blockIdx.y;
    const float* part = brn ? partb : parta;
    const float* gam  = brn ? gamb : gama;
    const float* bet  = brn ? betb : beta;
    const int nblk    = brn ? nblkb : nblka;
    const float invM  = brn ? invMb : invMa;
    float* scale = brn ? g_sb : g_sa;
    float* shift = brn ? g_hb : g_ha;

    const float* ps = part + (size_t)ch * nblk;
    const float* pq = part + (size_t)cout * nblk + (size_t)ch * nblk;
    float s = 0.f, s2 = 0.f;
    for (int i = t; i < nblk; i += 256) { s += ps[i]; s2 += pq[i]; }
#pragma unroll
    for (int o = 16; o; o >>= 1) {
        s  += __shfl_xor_sync(0xffffffffu, s, o);
        s2 += __shfl_xor_sync(0xffffffffu, s2, o);
    }
    __shared__ float sw[16];
    int w = t >> 5, l = t & 31;
    if (l == 0) { sw[w] = s; sw[8 + w] = s2; }
    __syncthreads();
    if (t == 0) {
        float a = 0.f, b = 0.f;
#pragma unroll
        for (int g = 0; g < 8; g++) { a += sw[g]; b += sw[8 + g]; }
        float m = a * invM;
        float v = fmaxf(b * invM - m * m, 0.f);
        float sc = gam[ch] * rsqrtf(v + 1e-5f);
        scale[ch] = sc;
        shift[ch] = bet[ch] - m * sc;
    }
}

// ---------------- edge-level stats (layer-0 branch b) ------------------------
__global__ void __launch_bounds__(256) estats1_k(const float* __restrict__ zb,
                                                 const int* __restrict__ ei,
                                                 float* __restrict__ part) {
    __shared__ float sh[512];
    const int t = threadIdx.x, blk = blockIdx.x;
    const int ch = t & 31, grp = t >> 5;
    const int e0 = blk * 256;
    float s = 0.f, s2 = 0.f;
#pragma unroll 4
    for (int i = grp; i < 256; i += 8) {
        int ge  = e0 + i;
        int b   = ge >> 17;
        int e   = ge & (EPB - 1);
        int ctr = (b << 14) + (e >> 3);
        int nbr = (b << 14) + ei[b * 2 * EPB + EPB + e];
        float d = zb[nbr * 32 + ch] - zb[ctr * 32 + ch];
        s += d; s2 += d * d;
    }
    sh[t] = s; sh[256 + t] = s2;
    __syncthreads();
    if (t < 32) {
        float a = 0.f, b2 = 0.f;
#pragma unroll
        for (int g = 0; g < 8; g++) { a += sh[g * 32 + t]; b2 += sh[256 + g * 32 + t]; }
        part[t * EBLK + blk]             = a;
        part[32 * EBLK + t * EBLK + blk] = b2;
    }
}

// ---------------- combine + fused cat-projection partial --------------------
template <int COUT, bool DIFF, bool WRITEH>
__global__ void __launch_bounds__(256) combine_k(const float* __restrict__ za,
                                                 const float* __restrict__ zb,
                                                 const int* __restrict__ ei,
                                                 __nv_bfloat16* __restrict__ xh,
                                                 __nv_bfloat16* __restrict__ xl,
                                                 const float* __restrict__ Wc,
                                                 float* __restrict__ dot) {
    constexpr int NPB = 256 / COUT;
    constexpr int WPN = COUT / 32;
    const int t = threadIdx.x;
    const int node = blockIdx.x * NPB + t / COUT;
    const int ch   = t & (COUT - 1);
    const int b = node >> 14, n = node & (NPTS - 1);
    const int* nb = ei + b * 2 * EPB + EPB + n * KNN;
    const int boff = b << 14;

    const float sb = g_sb[ch], hb = g_hb[ch];
    const float zc = DIFF ? zb[node * COUT + ch] : 0.f;
    float mx = -1e30f;
#pragma unroll
    for (int k = 0; k < KNN; k++) {
        int nn = boff + nb[k];
        float v = (zb[nn * COUT + ch] - zc) * sb + hb;
        v = v > 0.f ? v : 0.2f * v;
        mx = fmaxf(mx, v);
    }
    float va = za[node * COUT + ch] * g_sa[ch] + g_ha[ch];
    va = va > 0.f ? va : 0.2f * va;
    float v = va + mx;
    if (WRITEH) {
        __nv_bfloat16 h = __float2bfloat16(v);
        xh[node * COUT + ch] = h;
        xl[node * COUT + ch] = __float2bfloat16(v - __bfloat162float(h));
    }

    float d = v * Wc[ch];
#pragma unroll
    for (int o = 16; o; o >>= 1) d += __shfl_xor_sync(0xffffffffu, d, o);
    __shared__ float sd[8];
    int w = t >> 5;
    if ((t & 31) == 0) sd[w] = d;
    __syncthreads();
    if (t < NPB) {
        float s = 0.f;
#pragma unroll
        for (int g = 0; g < WPN; g++) s += sd[t * WPN + g];
        dot[blockIdx.x * NPB + t] = s;
    }
}

// ---------------- zcat: zc = sum of layer dots, emit stat partials ----------
__global__ void __launch_bounds__(256) zcat_k(float* __restrict__ part) {
    const int i = blockIdx.x * 256 + threadIdx.x;
    float s = g_dot[i] + g_dot[ROWS + i] + g_dot[2 * ROWS + i] + g_dot[3 * ROWS + i];
    g_zc[i] = s;
    float q = s * s;
#pragma unroll
    for (int o = 16; o; o >>= 1) {
        s += __shfl_xor_sync(0xffffffffu, s, o);
        q += __shfl_xor_sync(0xffffffffu, q, o);
    }
    __shared__ float sw[16];
    int w = threadIdx.x >> 5;
    if ((threadIdx.x & 31) == 0) { sw[w] = s; sw[8 + w] = q; }
    __syncthreads();
    if (threadIdx.x == 0) {
        float a = 0.f, b = 0.f;
#pragma unroll
        for (int g = 0; g < 8; g++) { a += sw[g]; b += sw[8 + g]; }
        part[blockIdx.x]       = a;
        part[256 + blockIdx.x] = b;
    }
}

// ---------------- final: fused cat-BN stats + BN(1ch) + lrelu + bias --------
__global__ void __launch_bounds__(256) final2_k(const float* __restrict__ part,
                                                const float* __restrict__ gct,
                                                const float* __restrict__ bct,
                                                const float* __restrict__ bias,
                                                float* __restrict__ out) {
    __shared__ float sw[16];
    __shared__ float s_sc, s_sh;
    const int t = threadIdx.x;
    float s = part[t], q = part[256 + t];
#pragma unroll
    for (int o = 16; o; o >>= 1) {
        s += __shfl_xor_sync(0xffffffffu, s, o);
        q += __shfl_xor_sync(0xffffffffu, q, o);
    }
    int w = t >> 5;
    if ((t & 31) == 0) { sw[w] = s; sw[8 + w] = q; }
    __syncthreads();
    if (t == 0) {
        float a = 0.f, b = 0.f;
#pragma unroll
        for (int g = 0; g < 8; g++) { a += sw[g]; b += sw[8 + g]; }
        const float invM = 1.0f / 65536.0f;
        float m = a * invM;
        float v = fmaxf(b * invM - m * m, 0.f);
        float sc = gct[0] * rsqrtf(v + 1e-5f);
        s_sc = sc;
        s_sh = bct[0] - m * sc;
    }
    __syncthreads();
    int i = blockIdx.x * 256 + t;
    float v = g_zc[i] * s_sc + s_sh;
    v = v > 0.f ? v : 0.2f * v;
    out[i] = v + bias[0];
}

// ---------------- host orchestration ----------------------------------------
extern "C" void kernel_launch(void* const* d_in, const int* in_sizes, int n_in,
                              void* d_out, int out_size) {
    const float* x   = (const float*)d_in[0];
    const int*   ei  = (const int*)d_in[1];
    const float* W0a = (const float*)d_in[2];
    const float* g0a = (const float*)d_in[3];
    const float* b0a = (const float*)d_in[4];
    const float* W0b = (const float*)d_in[5];
    const float* g0b = (const float*)d_in[6];
    const float* b0b = (const float*)d_in[7];
    const float* W1a = (const float*)d_in[8];
    const float* g1a = (const float*)d_in[9];
    const float* b1a = (const float*)d_in[10];
    const float* W1b = (const float*)d_in[11];
    const float* g1b = (const float*)d_in[12];
    const float* b1b = (const float*)d_in[13];
    const float* W2a = (const float*)d_in[14];
    const float* g2a = (const float*)d_in[15];
    const float* b2a = (const float*)d_in[16];
    const float* W2b = (const float*)d_in[17];
    const float* g2b = (const float*)d_in[18];
    const float* b2b = (const float*)d_in[19];
    const float* W3a = (const float*)d_in[20];
    const float* g3a = (const float*)d_in[21];
    const float* b3a = (const float*)d_in[22];
    const float* W3b = (const float*)d_in[23];
    const float* g3b = (const float*)d_in[24];
    const float* b3b = (const float*)d_in[25];
    const float* Wct = (const float*)d_in[26];
    const float* gct = (const float*)d_in[27];
    const float* bct = (const float*)d_in[28];
    const float* bia = (const float*)d_in[29];
    float* out = (float*)d_out;

    float *dt, *za, *zb, *pa, *pb;
    __nv_bfloat16 *x0h, *x0l, *x1h, *x1l, *x2h, *x2l;
    __nv_bfloat16 *w1h, *w1l, *w2h, *w2l, *w3h, *w3l;
    cudaGetSymbolAddress((void**)&dt, g_dot);
    cudaGetSymbolAddress((void**)&za, g_za);
    cudaGetSymbolAddress((void**)&zb, g_zb);
    cudaGetSymbolAddress((void**)&pa, g_pa);
    cudaGetSymbolAddress((void**)&pb, g_pb);
    cudaGetSymbolAddress((void**)&x0h, g_x0h);
    cudaGetSymbolAddress((void**)&x0l, g_x0l);
    cudaGetSymbolAddress((void**)&x1h, g_x1h);
    cudaGetSymbolAddress((void**)&x1l, g_x1l);
    cudaGetSymbolAddress((void**)&x2h, g_x2h);
    cudaGetSymbolAddress((void**)&x2l, g_x2l);
    cudaGetSymbolAddress((void**)&w1h, g_w1h);
    cudaGetSymbolAddress((void**)&w1l, g_w1l);
    cudaGetSymbolAddress((void**)&w2h, g_w2h);
    cudaGetSymbolAddress((void**)&w2l, g_w2l);
    cudaGetSymbolAddress((void**)&w3h, g_w3h);
    cudaGetSymbolAddress((void**)&w3l, g_w3l);

    const float invN = 1.0f / 65536.0f;
    const float invE = 1.0f / 524288.0f;

    const int smem1 = 128 * 132 * 4;             // 67584 > 4*128*40*2
    const int smem2 = 4 * 128 * (64 + 8) * 2;    // 73728
    const int smem3 = 4 * 128 * (128 + 8) * 2;   // 139264
    cudaFuncSetAttribute((const void*)tgemm_k<32, 1, true>,
                         cudaFuncAttributeMaxDynamicSharedMemorySize, smem1);
    cudaFuncSetAttribute((const void*)tgemm_k<64, 2, false>,
                         cudaFuncAttributeMaxDynamicSharedMemorySize, smem2);
    cudaFuncSetAttribute((const void*)tgemm_k<128, 4, false>,
                         cudaFuncAttributeMaxDynamicSharedMemorySize, smem3);

    // ---- weight prep (independent) ----
    wsplit_k<<<(2 * 64 * 32 + 255) / 256, 256>>>(W1a, W1b, 32, 64, w1h, w1l);
    wsplit_k<<<(2 * 128 * 64 + 255) / 256, 256>>>(W2a, W2b, 64, 128, w2h, w2l);
    wsplit_k<<<(2 * 256 * 128 + 255) / 256, 256>>>(W3a, W3b, 128, 256, w3h, w3l);

    // ---- layer 0: 8 -> 32 (FFMA2) ----
    gemm2_k<8, 32><<<dim3(GRIDX, 1, 2), 256>>>(x, W0a, W0b, za, zb, pa, pb);
    estats1_k<<<EBLK, 256>>>(zb, ei, pb);
    stats2d_k<<<dim3(32, 2), 256>>>(pa, pb, g0a, b0a, g0b, b0b, 32, GRIDX, EBLK, invN, invE);
    combine_k<32, true, true><<<ROWS * 32 / 256, 256>>>(za, zb, ei, x0h, x0l, Wct + 0, dt);

    // ---- layer 1: 32 -> 64 (mma.sync split, both branches one tile) ----
    tgemm_k<32, 1, true><<<dim3(GRIDX, 1), 256, smem1>>>(x0h, x0l, w1h, w1l, za, zb, pa, pb);
    stats2d_k<<<dim3(64, 2), 256>>>(pa, pb, g1a, b1a, g1b, b1b, 64, GRIDX, GRIDX, invN, invN);
    combine_k<64, false, true><<<ROWS * 64 / 256, 256>>>(za, zb, ei, x1h, x1l, Wct + 32, dt + ROWS);

    // ---- layer 2: 64 -> 128 (mma.sync split) ----
    tgemm_k<64, 2, false><<<dim3(GRIDX, 2), 256, smem2>>>(x1h, x1l, w2h, w2l, za, zb, pa, pb);
    stats2d_k<<<dim3(128, 2), 256>>>(pa, pb, g2a, b2a, g2b, b2b, 128, GRIDX, GRIDX, invN, invN);
    combine_k<128, false, true><<<ROWS * 128 / 256, 256>>>(za, zb, ei, x2h, x2l, Wct + 96, dt + 2 * ROWS);

    // ---- layer 3: 128 -> 256 (mma.sync split; x3 never materialized) ----
    tgemm_k<128, 4, false><<<dim3(GRIDX, 4), 256, smem3>>>(x2h, x2l, w3h, w3l, za, zb, pa, pb);
    stats2d_k<<<dim3(256, 2), 256>>>(pa, pb, g3a, b3a, g3b, b3b, 256, GRIDX, GRIDX, invN, invN);
    combine_k<256, false, false><<<ROWS, 256>>>(za, zb, ei, nullptr, nullptr, Wct + 224, dt + 3 * ROWS);

    // ---- cat sum + fused final BN/lrelu/bias ----
    zcat_k<<<256, 256>>>(pa);
    final2_k<<<ROWS / 256, 256>>>(pa, gct, bct, bia, out);
}

// round 17
// speedup vs baseline: 1.8830x; 1.0016x over previous
#include <cuda_runtime.h>
#include <cuda_bf16.h>
#include <cstdint>

// Problem constants
#define ROWS  65536      // B*N rows
#define NPTS  16384      // N
#define EPB   131072     // E per batch (N*K)
#define KNN   8
#define GRIDX 512        // ROWS / 128 row-blocks per GEMM
#define EBLK  2048       // estats blocks

// ---------------- scratch (device globals; no allocation allowed) ----------
__device__ __nv_bfloat16 g_x0h[ROWS * 32],  g_x0l[ROWS * 32];
__device__ __nv_bfloat16 g_x1h[ROWS * 64],  g_x1l[ROWS * 64];
__device__ __nv_bfloat16 g_x2h[ROWS * 128], g_x2l[ROWS * 128];
__device__ __nv_bfloat16 g_w1h[128 * 32],  g_w1l[128 * 32];    // [2*64 N, 32 K]
__device__ __nv_bfloat16 g_w2h[256 * 64],  g_w2l[256 * 64];    // [2*128 N, 64 K]
__device__ __nv_bfloat16 g_w3h[512 * 128], g_w3l[512 * 128];   // [2*256 N, 128 K]
__device__ float g_dot[ROWS * 4];
__device__ float g_za[ROWS * 256];
__device__ float g_zb[ROWS * 256];
__device__ float g_zc[ROWS];
__device__ float g_pa[256 * GRIDX * 2];
__device__ float g_pb[256 * GRIDX * 2];
__device__ float g_sa[256], g_ha[256];
__device__ float g_sb[256], g_hb[256];

// ---------------- helpers ----------------------------------------------------
__device__ __forceinline__ uint32_t smem_u32(const void* p) {
    uint32_t a;
    asm("{ .reg .u64 t; cvta.to.shared.u64 t, %1; cvt.u32.u64 %0, t; }" : "=r"(a) : "l"(p));
    return a;
}
__device__ __forceinline__ void ldsm4(uint32_t* r, uint32_t addr) {
    asm volatile("ldmatrix.sync.aligned.m8n8.x4.shared.b16 {%0,%1,%2,%3}, [%4];"
                 : "=r"(r[0]), "=r"(r[1]), "=r"(r[2]), "=r"(r[3]) : "r"(addr));
}
__device__ __forceinline__ void mma16816(float* d, const uint32_t* a, const uint32_t* b) {
    asm volatile(
        "mma.sync.aligned.m16n8k16.row.col.f32.bf16.bf16.f32 "
        "{%0,%1,%2,%3}, {%4,%5,%6,%7}, {%8,%9}, {%0,%1,%2,%3};"
        : "+f"(d[0]), "+f"(d[1]), "+f"(d[2]), "+f"(d[3])
        : "r"(a[0]), "r"(a[1]), "r"(a[2]), "r"(a[3]), "r"(b[0]), "r"(b[1]));
}
__device__ __forceinline__ void cpa16(uint32_t dst, const void* src) {
    asm volatile("cp.async.cg.shared.global [%0], [%1], 16;" :: "r"(dst), "l"(src));
}
#define CPA_COMMIT() asm volatile("cp.async.commit_group;" ::: "memory")
#define CPA_WAIT0()  asm volatile("cp.async.wait_group 0;" ::: "memory")
#define CPA_WAIT1()  asm volatile("cp.async.wait_group 1;" ::: "memory")

// ---------------- f32x2 helpers --------------------------------------------
__device__ __forceinline__ unsigned long long pack_dup(float a) {
    unsigned long long r;
    unsigned int ab = __float_as_uint(a);
    asm("mov.b64 %0, {%1, %1};" : "=l"(r) : "r"(ab));
    return r;
}
__device__ __forceinline__ float f2lo(unsigned long long v) {
    return __uint_as_float((unsigned int)(v & 0xffffffffULL));
}
__device__ __forceinline__ float f2hi(unsigned long long v) {
    return __uint_as_float((unsigned int)(v >> 32));
}

// ---------------- FFMA2 dual-branch GEMM (layer 0 only) ---------------------
template <int CIN, int COUT>
__global__ void __launch_bounds__(256) gemm2_k(const float* __restrict__ A,
                                               const float* __restrict__ Wa,
                                               const float* __restrict__ Wb,
                                               float* __restrict__ Ca,
                                               float* __restrict__ Cb,
                                               float* __restrict__ parta,
                                               float* __restrict__ partb) {
    constexpr int BM = 128;
    constexpr int BN = (COUT < 128) ? COUT : 128;
    constexpr int TM = 8;
    constexpr int TN = BN / 16;
    constexpr int NJ = TN / 2;
    constexpr int BK = 8;

    __shared__ float sh[BM * BK + BK * BN];
    float* As = sh;
    float* Ws = sh + BM * BK;

    const float* W    = blockIdx.z ? Wb : Wa;
    float*       C    = blockIdx.z ? Cb : Ca;
    float*       part = blockIdx.z ? partb : parta;

    const int t   = threadIdx.x;
    const int tx  = t & 15;
    const int ty  = t >> 4;
    const int row0 = blockIdx.x * BM;

    unsigned long long acc[TM][NJ];
#pragma unroll
    for (int m = 0; m < TM; m++)
#pragma unroll
        for (int j = 0; j < NJ; j++) acc[m][j] = 0ULL;

    for (int k0 = 0; k0 < CIN; k0 += BK) {
#pragma unroll
        for (int idx = t; idx < BM * BK; idx += 256) {
            int r = idx >> 3, c = idx & 7;
            As[r * BK + c] = A[(row0 + r) * CIN + k0 + c];
        }
#pragma unroll
        for (int idx = t; idx < BK * BN; idx += 256) {
            int kr = idx / BN, c = idx % BN;
            Ws[kr * BN + c] = W[(k0 + kr) * COUT + c];
        }
        __syncthreads();

#pragma unroll
        for (int k = 0; k < BK; k++) {
            unsigned long long a2[TM];
#pragma unroll
            for (int m = 0; m < TM; m++)
                a2[m] = pack_dup(As[(ty * TM + m) * BK + k]);
            unsigned long long w2[NJ];
#pragma unroll
            for (int j = 0; j < NJ; j++)
                w2[j] = *reinterpret_cast<const unsigned long long*>(
                    &Ws[k * BN + tx * 2 + 32 * j]);
#pragma unroll
            for (int m = 0; m < TM; m++)
#pragma unroll
                for (int j = 0; j < NJ; j++)
                    asm("fma.rn.f32x2 %0, %1, %2, %0;"
                        : "+l"(acc[m][j]) : "l"(a2[m]), "l"(w2[j]));
        }
        __syncthreads();
    }

#pragma unroll
    for (int m = 0; m < TM; m++) {
        int r = row0 + ty * TM + m;
#pragma unroll
        for (int j = 0; j < NJ; j++)
            *reinterpret_cast<unsigned long long*>(
                &C[r * COUT + tx * 2 + 32 * j]) = acc[m][j];
    }

    // fused stat partials
    float* red = sh;
#pragma unroll
    for (int j = 0; j < NJ; j++) {
        float s0 = 0.f, s1 = 0.f;
#pragma unroll
        for (int m = 0; m < TM; m++) { s0 += f2lo(acc[m][j]); s1 += f2hi(acc[m][j]); }
        red[ty * BN + tx * 2 + 32 * j]     = s0;
        red[ty * BN + tx * 2 + 32 * j + 1] = s1;
    }
    __syncthreads();
    if (t < BN) {
        float s = 0.f;
#pragma unroll
        for (int g = 0; g < 16; g++) s += red[g * BN + t];
        part[t * GRIDX + blockIdx.x] = s;
    }
    __syncthreads();
#pragma unroll
    for (int j = 0; j < NJ; j++) {
        float s0 = 0.f, s1 = 0.f;
#pragma unroll
        for (int m = 0; m < TM; m++) {
            float lo = f2lo(acc[m][j]), hi = f2hi(acc[m][j]);
            s0 += lo * lo; s1 += hi * hi;
        }
        red[ty * BN + tx * 2 + 32 * j]     = s0;
        red[ty * BN + tx * 2 + 32 * j + 1] = s1;
    }
    __syncthreads();
    if (t < BN) {
        float s = 0.f;
#pragma unroll
        for (int g = 0; g < 16; g++) s += red[g * BN + t];
        part[COUT * GRIDX + t * GRIDX + blockIdx.x] = s;
    }
}

// ---------------- mma.sync dual-branch GEMM (layers 1,2,3), bf16 split-2 ----
// C = Ahi@Whi + Ahi@Wlo + Alo@Whi, fp32 accum (HMMA).
// grid = GRIDX; A tile staged ONCE, loop over output chunks (128 cols each).
// W chunks staged via cp.async; double-buffered when CIN>=128.
// SPLITCOL (CHUNKS==1): cols 0-63 -> branch a, 64-127 -> branch b.
template <int CIN, int CHUNKS, bool SPLITCOL>
__global__ void __launch_bounds__(256) tgemm_k(
    const __nv_bfloat16* __restrict__ Ah, const __nv_bfloat16* __restrict__ Al,
    const __nv_bfloat16* __restrict__ Wh, const __nv_bfloat16* __restrict__ Wl,
    float* __restrict__ za, float* __restrict__ zb,
    float* __restrict__ pa, float* __restrict__ pb) {
    constexpr int NBB = SPLITCOL ? 64 : CHUNKS * 64;  // per-branch COUT
    constexpr int SA  = CIN + 8;         // smem row stride (elems), 16B-mult pad
    constexpr int KS  = CIN / 16;
    constexpr int V   = CIN / 8;         // 16B vectors per row
    constexpr bool DB = (CIN >= 128);    // double-buffer W stages
    constexpr int TILE = 128 * SA;       // elems per tile

    extern __shared__ __align__(16) char smem[];
    __nv_bfloat16* Ahs = (__nv_bfloat16*)smem;
    __nv_bfloat16* Als = Ahs + TILE;
    __nv_bfloat16* Wst = Als + TILE;     // stage s: Wh at Wst+2s*TILE, Wl at +（2s+1)*TILE
    float* sbuf = (float*)(Wst + (DB ? 4 : 2) * TILE);  // [128][4] sums
    float* qbuf = sbuf + 512;                            // [128][4] sumsqs

    const int t = threadIdx.x, lane = t & 31, wid = t >> 5;
    const int wm = wid & 3, wn = wid >> 2;            // 4x2 warp grid
    const int rb = blockIdx.x;
    const int g = lane >> 2, tg = lane & 3;

    // ---- prefetch W chunk 0 (stage 0) ----
    {
        const __nv_bfloat16* wh = Wh;
        const __nv_bfloat16* wl = Wl;
#pragma unroll
        for (int u = t; u < 128 * V; u += 256) {
            int row = u / V, k8 = (u % V) * 8;
            cpa16(smem_u32(&Wst[row * SA + k8]), &wh[row * CIN + k8]);
            cpa16(smem_u32(&Wst[TILE + row * SA + k8]), &wl[row * CIN + k8]);
        }
        CPA_COMMIT();
    }
    // ---- stage A tiles (hi, lo) once ----
    {
        const size_t ab = (size_t)rb * 128 * CIN;
#pragma unroll
        for (int u = t; u < 128 * V; u += 256) {
            int row = u / V, k8 = (u % V) * 8;
            *(uint4*)&Ahs[row * SA + k8] = *(const uint4*)&Ah[ab + row * CIN + k8];
            *(uint4*)&Als[row * SA + k8] = *(const uint4*)&Al[ab + row * CIN + k8];
        }
    }

    const uint32_t sAh = smem_u32(Ahs), sAl = smem_u32(Als);

    for (int c = 0; c < CHUNKS; c++) {
        const int stage = DB ? (c & 1) : 0;
        bool pref = DB && (c + 1 < CHUNKS);
        if (pref) {
            const int ns = (c + 1) & 1;
            const __nv_bfloat16* wh = Wh + (size_t)(c + 1) * 128 * CIN;
            const __nv_bfloat16* wl = Wl + (size_t)(c + 1) * 128 * CIN;
#pragma unroll
            for (int u = t; u < 128 * V; u += 256) {
                int row = u / V, k8 = (u % V) * 8;
                cpa16(smem_u32(&Wst[2 * ns * TILE + row * SA + k8]), &wh[row * CIN + k8]);
                cpa16(smem_u32(&Wst[(2 * ns + 1) * TILE + row * SA + k8]), &wl[row * CIN + k8]);
            }
            CPA_COMMIT();
        }
        if (pref) CPA_WAIT1(); else CPA_WAIT0();
        __syncthreads();

        const uint32_t sWh = smem_u32(&Wst[2 * stage * TILE]);
        const uint32_t sWl = smem_u32(&Wst[(2 * stage + 1) * TILE]);

        float acc[2][8][4];
#pragma unroll
        for (int mi = 0; mi < 2; mi++)
#pragma unroll
            for (int jn = 0; jn < 8; jn++)
#pragma unroll
                for (int q = 0; q < 4; q++) acc[mi][jn][q] = 0.f;

        for (int ks = 0; ks < KS; ks++) {
            uint32_t ah[2][4], al[2][4];
#pragma unroll
            for (int mi = 0; mi < 2; mi++) {
                int row = wm * 32 + mi * 16 + (lane & 15);
                uint32_t off = (uint32_t)((row * SA + ks * 16 + ((lane >> 4) << 3)) * 2);
                ldsm4(ah[mi], sAh + off);
                ldsm4(al[mi], sAl + off);
            }
#pragma unroll
            for (int bj = 0; bj < 4; bj++) {
                int rowb = wn * 64 + bj * 16 + ((lane >> 4) << 3) + (lane & 7);
                uint32_t koff = ((lane >> 3) & 1) * 8;
                uint32_t off = (uint32_t)((rowb * SA + ks * 16 + koff) * 2);
                uint32_t bh[4], bl[4];
                ldsm4(bh, sWh + off);
                ldsm4(bl, sWl + off);
#pragma unroll
                for (int mi = 0; mi < 2; mi++) {
                    mma16816(acc[mi][2 * bj],     ah[mi], bh);
                    mma16816(acc[mi][2 * bj + 1], ah[mi], bh + 2);
                    mma16816(acc[mi][2 * bj],     ah[mi], bl);
                    mma16816(acc[mi][2 * bj + 1], ah[mi], bl + 2);
                    mma16816(acc[mi][2 * bj],     al[mi], bh);
                    mma16816(acc[mi][2 * bj + 1], al[mi], bh + 2);
                }
            }
        }

        // ---- store C for this chunk ----
        const int br  = SPLITCOL ? 0 : (c >= CHUNKS / 2);
        const int gcb = SPLITCOL ? 0 : (c - br * (CHUNKS / 2)) * 128;
        {
            const int brS = SPLITCOL ? wn : br;
            float* out = brS ? zb : za;
#pragma unroll
            for (int mi = 0; mi < 2; mi++)
#pragma unroll
                for (int jn = 0; jn < 8; jn++) {
                    int col = SPLITCOL ? (jn * 8 + 2 * tg) : (wn * 64 + jn * 8 + 2 * tg);
                    int r0  = wm * 32 + mi * 16 + g;
                    size_t base = ((size_t)rb * 128 + r0) * NBB + gcb + col;
                    *(float2*)&out[base]           = make_float2(acc[mi][jn][0], acc[mi][jn][1]);
                    *(float2*)&out[base + 8 * NBB] = make_float2(acc[mi][jn][2], acc[mi][jn][3]);
                }
        }

        // ---- register-path BN stat partials ----
        float sv0[8], sv1[8], qv0[8], qv1[8];
#pragma unroll
        for (int jn = 0; jn < 8; jn++) {
            float a00 = acc[0][jn][0], a02 = acc[0][jn][2];
            float a10 = acc[1][jn][0], a12 = acc[1][jn][2];
            float a01 = acc[0][jn][1], a03 = acc[0][jn][3];
            float a11 = acc[1][jn][1], a13 = acc[1][jn][3];
            sv0[jn] = a00 + a02 + a10 + a12;
            sv1[jn] = a01 + a03 + a11 + a13;
            qv0[jn] = a00 * a00 + a02 * a02 + a10 * a10 + a12 * a12;
            qv1[jn] = a01 * a01 + a03 * a03 + a11 * a11 + a13 * a13;
        }
#pragma unroll
        for (int off = 4; off < 32; off <<= 1) {
#pragma unroll
            for (int jn = 0; jn < 8; jn++) {
                sv0[jn] += __shfl_xor_sync(0xffffffffu, sv0[jn], off);
                sv1[jn] += __shfl_xor_sync(0xffffffffu, sv1[jn], off);
                qv0[jn] += __shfl_xor_sync(0xffffffffu, qv0[jn], off);
                qv1[jn] += __shfl_xor_sync(0xffffffffu, qv1[jn], off);
            }
        }
        if (lane < 4) {
#pragma unroll
            for (int jn = 0; jn < 8; jn++) {
                int col = wn * 64 + jn * 8 + 2 * lane;
                sbuf[col * 4 + wm]       = sv0[jn];
                sbuf[(col + 1) * 4 + wm] = sv1[jn];
                qbuf[col * 4 + wm]       = qv0[jn];
                qbuf[(col + 1) * 4 + wm] = qv1[jn];
            }
        }
        __syncthreads();
        if (t < 128) {
            const int brS = SPLITCOL ? (t >= 64) : br;
            const int ch  = SPLITCOL ? (t & 63) : (gcb + t);
            float* part = brS ? pb : pa;
            float s = sbuf[t * 4] + sbuf[t * 4 + 1] + sbuf[t * 4 + 2] + sbuf[t * 4 + 3];
            float q = qbuf[t * 4] + qbuf[t * 4 + 1] + qbuf[t * 4 + 2] + qbuf[t * 4 + 3];
            part[ch * GRIDX + rb]               = s;
            part[NBB * GRIDX + ch * GRIDX + rb] = q;
        }
        __syncthreads();   // protects sbuf/qbuf and W-stage reuse

        if (!DB && c + 1 < CHUNKS) {
            const __nv_bfloat16* wh = Wh + (size_t)(c + 1) * 128 * CIN;
            const __nv_bfloat16* wl = Wl + (size_t)(c + 1) * 128 * CIN;
#pragma unroll
            for (int u = t; u < 128 * V; u += 256) {
                int row = u / V, k8 = (u % V) * 8;
                cpa16(smem_u32(&Wst[row * SA + k8]), &wh[row * CIN + k8]);
                cpa16(smem_u32(&Wst[TILE + row * SA + k8]), &wl[row * CIN + k8]);
            }
            CPA_COMMIT();
        }
    }
}

// ---------------- weight transpose + bf16 split ----------------------------
__global__ void wsplit_k(const float* __restrict__ Wa, const float* __restrict__ Wb,
                         int cin, int cout,
                         __nv_bfloat16* __restrict__ th, __nv_bfloat16* __restrict__ tl) {
    int idx = blockIdx.x * 256 + threadIdx.x;
    if (idx >= 2 * cout * cin) return;
    int n = idx / cin, k = idx % cin;
    float v = (n < cout) ? Wa[k * cout + n] : Wb[k * cout + (n - cout)];
    __nv_bfloat16 h = __float2bfloat16(v);
    th[idx] = h;
    tl[idx] = __float2bfloat16(v - __bfloat162float(h));
}

// ---------------- BN stats stage 2: both branches in one launch -------------
__global__ void __launch_bounds__(256) stats2d_k(const float* __restrict__ parta,
                                                 const float* __restrict__ partb,
                                                 const float* __restrict__ gama,
                                                 const float* __restrict__ beta,
                                                 const float* __restrict__ gamb,
                                                 const float* __restrict__ betb,
                                                 int cout, int nblka, int nblkb,
                                                 float invMa, float invMb) {
    const int ch = blockIdx.x, t = threadIdx.x, brn = blockIdx.y;
    const float* part = brn ? partb : parta;
    const float* gam  = brn ? gamb : gama;
    const float* bet  = brn ? betb : beta;
    const int nblk    = brn ? nblkb : nblka;
    const float invM  = brn ? invMb : invMa;
    float* scale = brn ? g_sb : g_sa;
    float* shift = brn ? g_hb : g_ha;

    const float* ps = part + (size_t)ch * nblk;
    const float* pq = part + (size_t)cout * nblk + (size_t)ch * nblk;
    float s = 0.f, s2 = 0.f;
    for (int i = t; i < nblk; i += 256) { s += ps[i]; s2 += pq[i]; }
#pragma unroll
    for (int o = 16; o; o >>= 1) {
        s  += __shfl_xor_sync(0xffffffffu, s, o);
        s2 += __shfl_xor_sync(0xffffffffu, s2, o);
    }
    __shared__ float sw[16];
    int w = t >> 5, l = t & 31;
    if (l == 0) { sw[w] = s; sw[8 + w] = s2; }
    __syncthreads();
    if (t == 0) {
        float a = 0.f, b = 0.f;
#pragma unroll
        for (int g = 0; g < 8; g++) { a += sw[g]; b += sw[8 + g]; }
        float m = a * invM;
        float v = fmaxf(b * invM - m * m, 0.f);
        float sc = gam[ch] * rsqrtf(v + 1e-5f);
        scale[ch] = sc;
        shift[ch] = bet[ch] - m * sc;
    }
}

// ---------------- edge-level stats (layer-0 branch b) ------------------------
__global__ void __launch_bounds__(256) estats1_k(const float* __restrict__ zb,
                                                 const int* __restrict__ ei,
                                                 float* __restrict__ part) {
    __shared__ float sh[512];
    const int t = threadIdx.x, blk = blockIdx.x;
    const int ch = t & 31, grp = t >> 5;
    const int e0 = blk * 256;
    float s = 0.f, s2 = 0.f;
#pragma unroll 4
    for (int i = grp; i < 256; i += 8) {
        int ge  = e0 + i;
        int b   = ge >> 17;
        int e   = ge & (EPB - 1);
        int ctr = (b << 14) + (e >> 3);
        int nbr = (b << 14) + ei[b * 2 * EPB + EPB + e];
        float d = zb[nbr * 32 + ch] - zb[ctr * 32 + ch];
        s += d; s2 += d * d;
    }
    sh[t] = s; sh[256 + t] = s2;
    __syncthreads();
    if (t < 32) {
        float a = 0.f, b2 = 0.f;
#pragma unroll
        for (int g = 0; g < 8; g++) { a += sh[g * 32 + t]; b2 += sh[256 + g * 32 + t]; }
        part[t * EBLK + blk]             = a;
        part[32 * EBLK + t * EBLK + blk] = b2;
    }
}

// ---------------- combine + fused cat-projection partial --------------------
template <int COUT, bool DIFF, bool WRITEH>
__global__ void __launch_bounds__(256) combine_k(const float* __restrict__ za,
                                                 const float* __restrict__ zb,
                                                 const int* __restrict__ ei,
                                                 __nv_bfloat16* __restrict__ xh,
                                                 __nv_bfloat16* __restrict__ xl,
                                                 const float* __restrict__ Wc,
                                                 float* __restrict__ dot) {
    constexpr int NPB = 256 / COUT;
    constexpr int WPN = COUT / 32;
    const int t = threadIdx.x;
    const int node = blockIdx.x * NPB + t / COUT;
    const int ch   = t & (COUT - 1);
    const int b = node >> 14, n = node & (NPTS - 1);
    const int* nb = ei + b * 2 * EPB + EPB + n * KNN;
    const int boff = b << 14;

    const float sb = g_sb[ch], hb = g_hb[ch];
    const float zc = DIFF ? zb[node * COUT + ch] : 0.f;
    float mx = -1e30f;
#pragma unroll
    for (int k = 0; k < KNN; k++) {
        int nn = boff + nb[k];
        float v = (zb[nn * COUT + ch] - zc) * sb + hb;
        v = v > 0.f ? v : 0.2f * v;
        mx = fmaxf(mx, v);
    }
    float va = za[node * COUT + ch] * g_sa[ch] + g_ha[ch];
    va = va > 0.f ? va : 0.2f * va;
    float v = va + mx;
    if (WRITEH) {
        __nv_bfloat16 h = __float2bfloat16(v);
        xh[node * COUT + ch] = h;
        xl[node * COUT + ch] = __float2bfloat16(v - __bfloat162float(h));
    }

    float d = v * Wc[ch];
#pragma unroll
    for (int o = 16; o; o >>= 1) d += __shfl_xor_sync(0xffffffffu, d, o);
    __shared__ float sd[8];
    int w = t >> 5;
    if ((t & 31) == 0) sd[w] = d;
    __syncthreads();
    if (t < NPB) {
        float s = 0.f;
#pragma unroll
        for (int g = 0; g < WPN; g++) s += sd[t * WPN + g];
        dot[blockIdx.x * NPB + t] = s;
    }
}

// ---------------- zcat: zc = sum of layer dots, emit stat partials ----------
__global__ void __launch_bounds__(256) zcat_k(float* __restrict__ part) {
    const int i = blockIdx.x * 256 + threadIdx.x;
    float s = g_dot[i] + g_dot[ROWS + i] + g_dot[2 * ROWS + i] + g_dot[3 * ROWS + i];
    g_zc[i] = s;
    float q = s * s;
#pragma unroll
    for (int o = 16; o; o >>= 1) {
        s += __shfl_xor_sync(0xffffffffu, s, o);
        q += __shfl_xor_sync(0xffffffffu, q, o);
    }
    __shared__ float sw[16];
    int w = threadIdx.x >> 5;
    if ((threadIdx.x & 31) == 0) { sw[w] = s; sw[8 + w] = q; }
    __syncthreads();
    if (threadIdx.x == 0) {
        float a = 0.f, b = 0.f;
#pragma unroll
        for (int g = 0; g < 8; g++) { a += sw[g]; b += sw[8 + g]; }
        part[blockIdx.x]       = a;
        part[256 + blockIdx.x] = b;
    }
}

// ---------------- final: fused cat-BN stats + BN(1ch) + lrelu + bias --------
__global__ void __launch_bounds__(256) final2_k(const float* __restrict__ part,
                                                const float* __restrict__ gct,
                                                const float* __restrict__ bct,
                                                const float* __restrict__ bias,
                                                float* __restrict__ out) {
    __shared__ float sw[16];
    __shared__ float s_sc, s_sh;
    const int t = threadIdx.x;
    float s = part[t], q = part[256 + t];
#pragma unroll
    for (int o = 16; o; o >>= 1) {
        s += __shfl_xor_sync(0xffffffffu, s, o);
        q += __shfl_xor_sync(0xffffffffu, q, o);
    }
    int w = t >> 5;
    if ((t & 31) == 0) { sw[w] = s; sw[8 + w] = q; }
    __syncthreads();
    if (t == 0) {
        float a = 0.f, b = 0.f;
#pragma unroll
        for (int g = 0; g < 8; g++) { a += sw[g]; b += sw[8 + g]; }
        const float invM = 1.0f / 65536.0f;
        float m = a * invM;
        float v = fmaxf(b * invM - m * m, 0.f);
        float sc = gct[0] * rsqrtf(v + 1e-5f);
        s_sc = sc;
        s_sh = bct[0] - m * sc;
    }
    __syncthreads();
    int i = blockIdx.x * 256 + t;
    float v = g_zc[i] * s_sc + s_sh;
    v = v > 0.f ? v : 0.2f * v;
    out[i] = v + bias[0];
}

// ---------------- host orchestration ----------------------------------------
extern "C" void kernel_launch(void* const* d_in, const int* in_sizes, int n_in,
                              void* d_out, int out_size) {
    const float* x   = (const float*)d_in[0];
    const int*   ei  = (const int*)d_in[1];
    const float* W0a = (const float*)d_in[2];
    const float* g0a = (const float*)d_in[3];
    const float* b0a = (const float*)d_in[4];
    const float* W0b = (const float*)d_in[5];
    const float* g0b = (const float*)d_in[6];
    const float* b0b = (const float*)d_in[7];
    const float* W1a = (const float*)d_in[8];
    const float* g1a = (const float*)d_in[9];
    const float* b1a = (const float*)d_in[10];
    const float* W1b = (const float*)d_in[11];
    const float* g1b = (const float*)d_in[12];
    const float* b1b = (const float*)d_in[13];
    const float* W2a = (const float*)d_in[14];
    const float* g2a = (const float*)d_in[15];
    const float* b2a = (const float*)d_in[16];
    const float* W2b = (const float*)d_in[17];
    const float* g2b = (const float*)d_in[18];
    const float* b2b = (const float*)d_in[19];
    const float* W3a = (const float*)d_in[20];
    const float* g3a = (const float*)d_in[21];
    const float* b3a = (const float*)d_in[22];
    const float* W3b = (const float*)d_in[23];
    const float* g3b = (const float*)d_in[24];
    const float* b3b = (const float*)d_in[25];
    const float* Wct = (const float*)d_in[26];
    const float* gct = (const float*)d_in[27];
    const float* bct = (const float*)d_in[28];
    const float* bia = (const float*)d_in[29];
    float* out = (float*)d_out;

    float *dt, *za, *zb, *pa, *pb;
    __nv_bfloat16 *x0h, *x0l, *x1h, *x1l, *x2h, *x2l;
    __nv_bfloat16 *w1h, *w1l, *w2h, *w2l, *w3h, *w3l;
    cudaGetSymbolAddress((void**)&dt, g_dot);
    cudaGetSymbolAddress((void**)&za, g_za);
    cudaGetSymbolAddress((void**)&zb, g_zb);
    cudaGetSymbolAddress((void**)&pa, g_pa);
    cudaGetSymbolAddress((void**)&pb, g_pb);
    cudaGetSymbolAddress((void**)&x0h, g_x0h);
    cudaGetSymbolAddress((void**)&x0l, g_x0l);
    cudaGetSymbolAddress((void**)&x1h, g_x1h);
    cudaGetSymbolAddress((void**)&x1l, g_x1l);
    cudaGetSymbolAddress((void**)&x2h, g_x2h);
    cudaGetSymbolAddress((void**)&x2l, g_x2l);
    cudaGetSymbolAddress((void**)&w1h, g_w1h);
    cudaGetSymbolAddress((void**)&w1l, g_w1l);
    cudaGetSymbolAddress((void**)&w2h, g_w2h);
    cudaGetSymbolAddress((void**)&w2l, g_w2l);
    cudaGetSymbolAddress((void**)&w3h, g_w3h);
    cudaGetSymbolAddress((void**)&w3l, g_w3l);

    const float invN = 1.0f / 65536.0f;
    const float invE = 1.0f / 524288.0f;

    // smem: A(2 tiles) + W(2 or 4 tiles) + 4KB stat buf
    const int smem1 = 4 * 128 * (32 + 8) * 2 + 4096;    // 45056
    const int smem2 = 4 * 128 * (64 + 8) * 2 + 4096;    // 77824
    const int smem3 = 6 * 128 * (128 + 8) * 2 + 4096;   // 212992
    cudaFuncSetAttribute((const void*)tgemm_k<32, 1, true>,
                         cudaFuncAttributeMaxDynamicSharedMemorySize, smem1);
    cudaFuncSetAttribute((const void*)tgemm_k<64, 2, false>,
                         cudaFuncAttributeMaxDynamicSharedMemorySize, smem2);
    cudaFuncSetAttribute((const void*)tgemm_k<128, 4, false>,
                         cudaFuncAttributeMaxDynamicSharedMemorySize, smem3);

    // ---- weight prep (independent) ----
    wsplit_k<<<(2 * 64 * 32 + 255) / 256, 256>>>(W1a, W1b, 32, 64, w1h, w1l);
    wsplit_k<<<(2 * 128 * 64 + 255) / 256, 256>>>(W2a, W2b, 64, 128, w2h, w2l);
    wsplit_k<<<(2 * 256 * 128 + 255) / 256, 256>>>(W3a, W3b, 128, 256, w3h, w3l);

    // ---- layer 0: 8 -> 32 (FFMA2) ----
    gemm2_k<8, 32><<<dim3(GRIDX, 1, 2), 256>>>(x, W0a, W0b, za, zb, pa, pb);
    estats1_k<<<EBLK, 256>>>(zb, ei, pb);
    stats2d_k<<<dim3(32, 2), 256>>>(pa, pb, g0a, b0a, g0b, b0b, 32, GRIDX, EBLK, invN, invE);
    combine_k<32, true, true><<<ROWS * 32 / 256, 256>>>(za, zb, ei, x0h, x0l, Wct + 0, dt);

    // ---- layer 1: 32 -> 64 (mma.sync split, both branches one tile) ----
    tgemm_k<32, 1, true><<<GRIDX, 256, smem1>>>(x0h, x0l, w1h, w1l, za, zb, pa, pb);
    stats2d_k<<<dim3(64, 2), 256>>>(pa, pb, g1a, b1a, g1b, b1b, 64, GRIDX, GRIDX, invN, invN);
    combine_k<64, false, true><<<ROWS * 64 / 256, 256>>>(za, zb, ei, x1h, x1l, Wct + 32, dt + ROWS);

    // ---- layer 2: 64 -> 128 (mma.sync split, chunk loop) ----
    tgemm_k<64, 2, false><<<GRIDX, 256, smem2>>>(x1h, x1l, w2h, w2l, za, zb, pa, pb);
    stats2d_k<<<dim3(128, 2), 256>>>(pa, pb, g2a, b2a, g2b, b2b, 128, GRIDX, GRIDX, invN, invN);
    combine_k<128, false, true><<<ROWS * 128 / 256, 256>>>(za, zb, ei, x2h, x2l, Wct + 96, dt + 2 * ROWS);

    // ---- layer 3: 128 -> 256 (mma.sync split, chunk loop + W double-buffer) ----
    tgemm_k<128, 4, false><<<GRIDX, 256, smem3>>>(x2h, x2l, w3h, w3l, za, zb, pa, pb);
    stats2d_k<<<dim3(256, 2), 256>>>(pa, pb, g3a, b3a, g3b, b3b, 256, GRIDX, GRIDX, invN, invN);
    combine_k<256, false, false><<<ROWS, 256>>>(za, zb, ei, nullptr, nullptr, Wct + 224, dt + 3 * ROWS);

    // ---- cat sum + fused final BN/lrelu/bias ----
    zcat_k<<<256, 256>>>(pa);
    final2_k<<<ROWS / 256, 256>>>(pa, gct, bct, bia, out);
}